// round 3
// baseline (speedup 1.0000x reference)
#include <cuda_runtime.h>
#include <math.h>

#define BATCH 4
#define C1N 128
#define H1N 128
#define W1N 128
#define C2N 64
#define H2N 64
#define W2N 64
#define LP 4096          // H2*W2 positions / patches
#define KPATCH 576       // C2 * 3 * 3
#define MRAW 2048        // C1 * 4 * 4
#define SCALE_F 10.0f

// ---- scratch (device globals: allocation-free) ----
__device__ float g_A[LP * KPATCH];       // im2col(x2)  [p][k]   9.4 MB
__device__ float g_invn[LP];
__device__ float g_mm[LP];
__device__ float g_S[(size_t)LP * LP];   // scores -> softmax P  [p][q]  64 MB
__device__ float g_raw[(size_t)MRAW * LP];  // rawT [m][q]  32 MB
__device__ float g_cols[(size_t)MRAW * LP]; // GEMM2 out [m][pos] 32 MB
__device__ float g_y[(size_t)BATCH * C1N * H1N * W1N]; // 32 MB

// ------------------------------------------------------------------
// im2col of x2 (k=3,s=1,pad=1) + patch inverse norms
// ------------------------------------------------------------------
__global__ void im2col_norm_kernel(const float* __restrict__ x2) {
    int p = blockIdx.x;
    int pi = p >> 6, pj = p & 63;
    int tid = threadIdx.x;
    float ss = 0.f;
    for (int k = tid; k < KPATCH; k += 256) {
        int c = k / 9, ki = k % 9;
        int ky = ki / 3, kx = ki % 3;
        int yy = pi - 1 + ky, xx = pj - 1 + kx;
        float v = 0.f;
        if (yy >= 0 && yy < H2N && xx >= 0 && xx < W2N)
            v = x2[(c * H2N + yy) * W2N + xx];
        g_A[p * KPATCH + k] = v;
        ss += v * v;
    }
    __shared__ float red[256];
    red[tid] = ss;
    __syncthreads();
    for (int s = 128; s > 0; s >>= 1) {
        if (tid < s) red[tid] += red[tid + s];
        __syncthreads();
    }
    if (tid == 0) {
        float n = sqrtf(red[0]);
        g_invn[p] = 1.f / fmaxf(n, 1e-4f);
    }
}

// ------------------------------------------------------------------
// mask patches (k=4,s=2,pad=1): mm[q] = (sum == 0) ? 1 : 0
// ------------------------------------------------------------------
__global__ void mask_patch_kernel(const float* __restrict__ mask) {
    int q = blockIdx.x * blockDim.x + threadIdx.x;
    if (q >= LP) return;
    int qi = q >> 6, qj = q & 63;
    float s = 0.f;
    for (int ky = 0; ky < 4; ky++)
        for (int kx = 0; kx < 4; kx++) {
            int yy = 2 * qi - 1 + ky, xx = 2 * qj - 1 + kx;
            if (yy >= 0 && yy < H1N && xx >= 0 && xx < W1N)
                s += mask[yy * W1N + xx];
        }
    g_mm[q] = (s == 0.f) ? 1.f : 0.f;
}

// ------------------------------------------------------------------
// NT GEMM body: C[m][n] = (sum_k A[m][k]*B[n][k]) * (colScale?colScale[n]:1)
// 128x128 block tile, BK=8, 256 threads, 8x8 per thread
// ------------------------------------------------------------------
__device__ __forceinline__ void gemm_nt_body(
    const float* __restrict__ A, const float* __restrict__ B, float* __restrict__ C,
    int K, int lda, int ldb, int ldc, const float* __restrict__ colScale)
{
    __shared__ float As[8][128];
    __shared__ float Bs[8][128];
    int tid = threadIdx.x;
    int m0 = blockIdx.y * 128, n0 = blockIdx.x * 128;
    int loadRow = tid >> 1;
    int loadCol = (tid & 1) * 4;
    const float* Aptr = A + (size_t)(m0 + loadRow) * lda + loadCol;
    const float* Bptr = B + (size_t)(n0 + loadRow) * ldb + loadCol;
    int ty = tid >> 4, tx = tid & 15;

    float acc[8][8];
#pragma unroll
    for (int i = 0; i < 8; i++)
#pragma unroll
        for (int j = 0; j < 8; j++) acc[i][j] = 0.f;

    for (int k0 = 0; k0 < K; k0 += 8) {
        float4 av = *(const float4*)(Aptr + k0);
        float4 bv = *(const float4*)(Bptr + k0);
        As[loadCol + 0][loadRow] = av.x;
        As[loadCol + 1][loadRow] = av.y;
        As[loadCol + 2][loadRow] = av.z;
        As[loadCol + 3][loadRow] = av.w;
        Bs[loadCol + 0][loadRow] = bv.x;
        Bs[loadCol + 1][loadRow] = bv.y;
        Bs[loadCol + 2][loadRow] = bv.z;
        Bs[loadCol + 3][loadRow] = bv.w;
        __syncthreads();
#pragma unroll
        for (int k = 0; k < 8; k++) {
            float4 a0 = *(const float4*)&As[k][ty * 8];
            float4 a1 = *(const float4*)&As[k][ty * 8 + 4];
            float4 b0 = *(const float4*)&Bs[k][tx * 8];
            float4 b1 = *(const float4*)&Bs[k][tx * 8 + 4];
            float a[8] = {a0.x, a0.y, a0.z, a0.w, a1.x, a1.y, a1.z, a1.w};
            float b[8] = {b0.x, b0.y, b0.z, b0.w, b1.x, b1.y, b1.z, b1.w};
#pragma unroll
            for (int i = 0; i < 8; i++)
#pragma unroll
                for (int j = 0; j < 8; j++) acc[i][j] += a[i] * b[j];
        }
        __syncthreads();
    }

    float sc[8];
#pragma unroll
    for (int j = 0; j < 8; j++)
        sc[j] = colScale ? colScale[n0 + tx * 8 + j] : 1.f;
#pragma unroll
    for (int i = 0; i < 8; i++) {
        int row = m0 + ty * 8 + i;
        float4 o0, o1;
        o0.x = acc[i][0] * sc[0]; o0.y = acc[i][1] * sc[1];
        o0.z = acc[i][2] * sc[2]; o0.w = acc[i][3] * sc[3];
        o1.x = acc[i][4] * sc[4]; o1.y = acc[i][5] * sc[5];
        o1.z = acc[i][6] * sc[6]; o1.w = acc[i][7] * sc[7];
        *(float4*)(C + (size_t)row * ldc + n0 + tx * 8) = o0;
        *(float4*)(C + (size_t)row * ldc + n0 + tx * 8 + 4) = o1;
    }
}

__global__ void __launch_bounds__(256) gemm1_kernel() {
    // S[p][q] = <A_p, A_q> * invn[q];  M=N=4096, K=576
    gemm_nt_body(g_A, g_A, g_S, KPATCH, KPATCH, KPATCH, LP, g_invn);
}
__global__ void __launch_bounds__(256) gemm2_kernel() {
    // cols[m][pos] = sum_q rawT[m][q] * P[pos][q]; M=2048, N=4096, K=4096
    gemm_nt_body(g_raw, g_S, g_cols, LP, LP, LP, LP, nullptr);
}

// ------------------------------------------------------------------
// masked softmax over q for each row p (in-place on g_S)
// ------------------------------------------------------------------
__global__ void __launch_bounds__(256) softmax_kernel(const float* __restrict__ mask_all) {
    int p = blockIdx.x;
    int tid = threadIdx.x;
    float map = mask_all[p];
    float* row = g_S + (size_t)p * LP;

    float v[16];
    float lmax = -1e30f;
#pragma unroll
    for (int i = 0; i < 16; i++) {
        int q = tid + i * 256;
        float x = row[q] * g_mm[q] * map;
        v[i] = x;
        lmax = fmaxf(lmax, x);
    }
    __shared__ float red[256];
    red[tid] = lmax;
    __syncthreads();
    for (int s = 128; s > 0; s >>= 1) {
        if (tid < s) red[tid] = fmaxf(red[tid], red[tid + s]);
        __syncthreads();
    }
    float gmax = red[0];
    __syncthreads();

    float lsum = 0.f;
#pragma unroll
    for (int i = 0; i < 16; i++) {
        float e = expf(SCALE_F * (v[i] - gmax));
        v[i] = e;
        lsum += e;
    }
    red[tid] = lsum;
    __syncthreads();
    for (int s = 128; s > 0; s >>= 1) {
        if (tid < s) red[tid] += red[tid + s];
        __syncthreads();
    }
    float inv = 1.f / red[0];
#pragma unroll
    for (int i = 0; i < 16; i++) {
        int q = tid + i * 256;
        row[q] = fmaxf(v[i] * inv * g_mm[q] * map, 1e-8f);
    }
}

// ------------------------------------------------------------------
// rawT[m][q] = x1 patch gather (k=4, s=2, pad=1), m = o*16 + ky*4 + kx
// ------------------------------------------------------------------
__global__ void fill_raw_kernel(const float* __restrict__ x1) {
    int q = blockIdx.x * blockDim.x + threadIdx.x;
    int m = blockIdx.y;
    int o = m >> 4, kk = m & 15;
    int ky = kk >> 2, kx = kk & 3;
    int qi = q >> 6, qj = q & 63;
    int yy = 2 * qi - 1 + ky, xx = 2 * qj - 1 + kx;
    float v = 0.f;
    if (yy >= 0 && yy < H1N && xx >= 0 && xx < W1N)
        v = x1[(o * H1N + yy) * W1N + xx];
    g_raw[(size_t)m * LP + q] = v;
}

// ------------------------------------------------------------------
// col2im gather: y[o,Y,X] = 0.25 * sum over <=4 entries of g_cols
// ------------------------------------------------------------------
__global__ void col2im_kernel(int b) {
    int idx = blockIdx.x * blockDim.x + threadIdx.x;
    int X = idx & 127;
    int Y = (idx >> 7) & 127;
    int o = idx >> 14;
    float acc = 0.f;
    int ky0 = (Y & 1) ? 0 : 1;
    int kx0 = (X & 1) ? 0 : 1;
#pragma unroll
    for (int t = 0; t < 2; t++) {
        int ky = ky0 + 2 * t;
        int i = (Y + 1 - ky) >> 1;
        if (i < 0 || i >= 64) continue;
#pragma unroll
        for (int u = 0; u < 2; u++) {
            int kx = kx0 + 2 * u;
            int j = (X + 1 - kx) >> 1;
            if (j < 0 || j >= 64) continue;
            acc += g_cols[(size_t)(o * 16 + ky * 4 + kx) * LP + i * 64 + j];
        }
    }
    g_y[(size_t)b * C1N * H1N * W1N + idx] = acc * 0.25f;
}

// ------------------------------------------------------------------
// final: 4 grouped dilated 3x3 convs (rates 1,2,4,8) + bias + relu
// block: one (b, g, 16x16 spatial tile); 16 out-channels in registers
// ------------------------------------------------------------------
__global__ void __launch_bounds__(256) final_conv_kernel(
    const float* __restrict__ w, const float* __restrict__ bias, float* __restrict__ out)
{
    int tile = blockIdx.x;
    int g = blockIdx.y;
    int b = blockIdx.z;
    int r = 1 << g;  // rates 1,2,4,8
    int ty0 = (tile >> 3) * 16, tx0 = (tile & 7) * 16;
    int HW = 16 + 2 * r;
    __shared__ float yt[32 * 32];
    __shared__ float ws[144];
    int tid = threadIdx.x;
    int py = tid >> 4, px = tid & 15;

    float acc[16];
#pragma unroll
    for (int i = 0; i < 16; i++) acc[i] = 0.f;

    const float* yb = g_y + (size_t)b * C1N * H1N * W1N;
    for (int c = 0; c < C1N; c++) {
        for (int idx = tid; idx < HW * HW; idx += 256) {
            int iy = idx / HW, ix = idx % HW;
            int gy = ty0 - r + iy, gx = tx0 - r + ix;
            float v = 0.f;
            if (gy >= 0 && gy < H1N && gx >= 0 && gx < W1N)
                v = yb[(c * H1N + gy) * W1N + gx];
            yt[idx] = v;
        }
        if (tid < 144)
            ws[tid] = w[((g * 16 + tid / 9) * C1N + c) * 9 + tid % 9];
        __syncthreads();
#pragma unroll
        for (int ky = 0; ky < 3; ky++)
#pragma unroll
            for (int kx = 0; kx < 3; kx++) {
                float v = yt[(py + ky * r) * HW + px + kx * r];
#pragma unroll
                for (int oc = 0; oc < 16; oc++)
                    acc[oc] += v * ws[oc * 9 + ky * 3 + kx];
            }
        __syncthreads();
    }
    int Y = ty0 + py, X = tx0 + px;
#pragma unroll
    for (int oc = 0; oc < 16; oc++) {
        float o = acc[oc] + bias[g * 16 + oc];
        out[((size_t)(b * 64 + g * 16 + oc) * H1N + Y) * W1N + X] = fmaxf(o, 0.f);
    }
}

// ------------------------------------------------------------------
extern "C" void kernel_launch(void* const* d_in, const int* in_sizes, int n_in,
                              void* d_out, int out_size) {
    const float* x1       = (const float*)d_in[0];  // [4,128,128,128]
    const float* x2       = (const float*)d_in[1];  // [4,64,64,64]
    const float* mask     = (const float*)d_in[2];  // [4,1,128,128]
    const float* mask_all = (const float*)d_in[3];  // [4,1,64,64]
    const float* conv_w   = (const float*)d_in[4];  // [4,16,128,3,3]
    const float* conv_b   = (const float*)d_in[5];  // [4,16]
    float* out = (float*)d_out;

    for (int b = 0; b < BATCH; b++) {
        im2col_norm_kernel<<<LP, 256>>>(x2 + (size_t)b * C2N * H2N * W2N);
        mask_patch_kernel<<<LP / 256, 256>>>(mask + (size_t)b * H1N * W1N);
        gemm1_kernel<<<dim3(32, 32), 256>>>();
        softmax_kernel<<<LP, 256>>>(mask_all + (size_t)b * LP);
        fill_raw_kernel<<<dim3(LP / 256, MRAW), 256>>>(x1 + (size_t)b * C1N * H1N * W1N);
        gemm2_kernel<<<dim3(32, 16), 256>>>();
        col2im_kernel<<<(C1N * H1N * W1N) / 256, 256>>>(b);
    }
    final_conv_kernel<<<dim3(64, 4, 4), 256>>>(conv_w, conv_b, out);
}

// round 5
// speedup vs baseline: 1.7638x; 1.7638x over previous
#include <cuda_runtime.h>
#include <cuda_bf16.h>
#include <math.h>
#include <stdint.h>

#define BATCH 4
#define C1N 128
#define H1N 128
#define W1N 128
#define C2N 64
#define H2N 64
#define W2N 64
#define LP 4096          // H2*W2 positions / patches
#define KPATCH 576       // C2 * 3 * 3
#define MRAW 2048        // C1 * 4 * 4
#define SCALE_F 10.0f

// ---- scratch (device globals: allocation-free) ----
__device__ float g_A[LP * KPATCH];          // im2col(x2)  [p][k]
__device__ float g_invn[LP];
__device__ float g_mm[LP];
__device__ float g_S[(size_t)LP * LP];      // scores -> softmax P  [p][q]
__device__ float g_raw[(size_t)MRAW * LP];  // rawT [m][q]
__device__ float g_cols[(size_t)MRAW * LP]; // GEMM2 out [m][pos]
__device__ float g_y[(size_t)BATCH * C1N * H1N * W1N];

// ==================================================================
// mma.sync wrappers (base PTX, works at compute_103)
// ==================================================================
__device__ __forceinline__ void mma_tf32(float d[4], const uint32_t a[4], const uint32_t b[2]) {
    asm volatile(
        "mma.sync.aligned.m16n8k8.row.col.f32.tf32.tf32.f32 "
        "{%0,%1,%2,%3},{%4,%5,%6,%7},{%8,%9},{%0,%1,%2,%3};"
        : "+f"(d[0]), "+f"(d[1]), "+f"(d[2]), "+f"(d[3])
        : "r"(a[0]), "r"(a[1]), "r"(a[2]), "r"(a[3]), "r"(b[0]), "r"(b[1]));
}
__device__ __forceinline__ void mma_bf16(float d[4], const uint32_t a[4], const uint32_t b[2]) {
    asm volatile(
        "mma.sync.aligned.m16n8k16.row.col.f32.bf16.bf16.f32 "
        "{%0,%1,%2,%3},{%4,%5,%6,%7},{%8,%9},{%0,%1,%2,%3};"
        : "+f"(d[0]), "+f"(d[1]), "+f"(d[2]), "+f"(d[3])
        : "r"(a[0]), "r"(a[1]), "r"(a[2]), "r"(a[3]), "r"(b[0]), "r"(b[1]));
}
__device__ __forceinline__ uint32_t f2tf32(float x) {
    uint32_t r;
    asm("cvt.rna.tf32.f32 %0, %1;" : "=r"(r) : "f"(x));
    return r;
}

// ==================================================================
// GEMM1: 3xTF32 split. C[m][n] = <A_m, B_n> * colScale[n]
// M=N=4096, K=576. Block 128x128, BK=16, 8 warps (32x64 each).
// ==================================================================
#define T_STRIDE 20     // 16 + 4 pad (fp32 words per row)

__global__ void __launch_bounds__(256) gemm1_mma() {
    __shared__ float sAh[128 * T_STRIDE], sAl[128 * T_STRIDE];
    __shared__ float sBh[128 * T_STRIDE], sBl[128 * T_STRIDE];
    const float* A = g_A;
    const float* B = g_A;
    float* C = g_S;
    const int lda = KPATCH, ldc = LP, K = KPATCH;

    int t = threadIdx.x;
    int m0 = blockIdx.y * 128, n0 = blockIdx.x * 128;
    int wid = t >> 5, lane = t & 31;
    int wm = (wid >> 1) * 32, wn = (wid & 1) * 64;
    int g = lane >> 2, tig = lane & 3;

    float acc[2][8][4] = {};

    int lm = t >> 2;          // row (+64*i)
    int lc = (t & 3) * 4;     // k offset within BK=16 chunk

    float4 ra[2], rb[2];
    const int NC = K / 16;
#pragma unroll 1
    for (int i = 0; i < 2; i++) {
        ra[i] = *(const float4*)(A + (size_t)(m0 + lm + 64 * i) * lda + lc);
        rb[i] = *(const float4*)(B + (size_t)(n0 + lm + 64 * i) * lda + lc);
    }
    for (int ci = 0; ci < NC; ci++) {
        if (ci > 0) __syncthreads();
#pragma unroll
        for (int i = 0; i < 2; i++) {
            int base = (lm + 64 * i) * T_STRIDE + lc;
            float4 v = ra[i];
            float h0 = __uint_as_float(f2tf32(v.x)), h1 = __uint_as_float(f2tf32(v.y));
            float h2 = __uint_as_float(f2tf32(v.z)), h3 = __uint_as_float(f2tf32(v.w));
            *(float4*)&sAh[base] = make_float4(h0, h1, h2, h3);
            *(float4*)&sAl[base] = make_float4(v.x - h0, v.y - h1, v.z - h2, v.w - h3);
            v = rb[i];
            h0 = __uint_as_float(f2tf32(v.x)); h1 = __uint_as_float(f2tf32(v.y));
            h2 = __uint_as_float(f2tf32(v.z)); h3 = __uint_as_float(f2tf32(v.w));
            *(float4*)&sBh[base] = make_float4(h0, h1, h2, h3);
            *(float4*)&sBl[base] = make_float4(v.x - h0, v.y - h1, v.z - h2, v.w - h3);
        }
        __syncthreads();
        if (ci + 1 < NC) {
            int k0 = (ci + 1) * 16;
#pragma unroll
            for (int i = 0; i < 2; i++) {
                ra[i] = *(const float4*)(A + (size_t)(m0 + lm + 64 * i) * lda + k0 + lc);
                rb[i] = *(const float4*)(B + (size_t)(n0 + lm + 64 * i) * lda + k0 + lc);
            }
        }
#pragma unroll
        for (int s = 0; s < 2; s++) {
            uint32_t ah[2][4], al[2][4], bh[8][2], bl[8][2];
#pragma unroll
            for (int mt = 0; mt < 2; mt++) {
                int base = (wm + mt * 16 + g) * T_STRIDE + s * 8 + tig;
                ah[mt][0] = __float_as_uint(sAh[base]);
                ah[mt][1] = __float_as_uint(sAh[base + 8 * T_STRIDE]);
                ah[mt][2] = __float_as_uint(sAh[base + 4]);
                ah[mt][3] = __float_as_uint(sAh[base + 8 * T_STRIDE + 4]);
                al[mt][0] = __float_as_uint(sAl[base]);
                al[mt][1] = __float_as_uint(sAl[base + 8 * T_STRIDE]);
                al[mt][2] = __float_as_uint(sAl[base + 4]);
                al[mt][3] = __float_as_uint(sAl[base + 8 * T_STRIDE + 4]);
            }
#pragma unroll
            for (int nt = 0; nt < 8; nt++) {
                int base = (wn + nt * 8 + g) * T_STRIDE + s * 8 + tig;
                bh[nt][0] = __float_as_uint(sBh[base]);
                bh[nt][1] = __float_as_uint(sBh[base + 4]);
                bl[nt][0] = __float_as_uint(sBl[base]);
                bl[nt][1] = __float_as_uint(sBl[base + 4]);
            }
#pragma unroll
            for (int mt = 0; mt < 2; mt++)
#pragma unroll
                for (int nt = 0; nt < 8; nt++) {
                    mma_tf32(acc[mt][nt], ah[mt], bh[nt]);
                    mma_tf32(acc[mt][nt], ah[mt], bl[nt]);
                    mma_tf32(acc[mt][nt], al[mt], bh[nt]);
                }
        }
    }
    // epilogue with column scale
#pragma unroll
    for (int mt = 0; mt < 2; mt++) {
        int row = m0 + wm + mt * 16 + g;
#pragma unroll
        for (int nt = 0; nt < 8; nt++) {
            int col = n0 + wn + nt * 8 + 2 * tig;
            float s0 = __ldg(&g_invn[col]);
            float s1 = __ldg(&g_invn[col + 1]);
            *(float2*)(C + (size_t)row * ldc + col) =
                make_float2(acc[mt][nt][0] * s0, acc[mt][nt][1] * s1);
            *(float2*)(C + (size_t)(row + 8) * ldc + col) =
                make_float2(acc[mt][nt][2] * s0, acc[mt][nt][3] * s1);
        }
    }
}

// ==================================================================
// GEMM2: bf16 3-MMA split. cols[m][p] = sum_q raw[m][q] * P[p][q]
// M=2048, N=4096, K=4096. Block 128x128, BK=32, 8 warps.
// ==================================================================
#define B_STRIDE 18     // (32 + 4 pad) bf16 = 18 b32 words per row

__global__ void __launch_bounds__(256) gemm2_mma() {
    __shared__ uint32_t sAh[128 * B_STRIDE], sAl[128 * B_STRIDE];
    __shared__ uint32_t sBh[128 * B_STRIDE], sBl[128 * B_STRIDE];
    const float* A = g_raw;
    const float* B = g_S;
    float* C = g_cols;
    const int lda = LP, ldb = LP, ldc = LP, K = LP;

    int t = threadIdx.x;
    int m0 = blockIdx.y * 128, n0 = blockIdx.x * 128;
    int wid = t >> 5, lane = t & 31;
    int wm = (wid >> 1) * 32, wn = (wid & 1) * 64;
    int g = lane >> 2, tig = lane & 3;

    float acc[2][8][4] = {};

    int lm = t >> 3;          // row (+32*i)
    int lc = (t & 7) * 4;     // k offset within BK=32 chunk

    float4 ra[4], rb[4];
    const int NC = K / 32;
#pragma unroll
    for (int i = 0; i < 4; i++) {
        ra[i] = *(const float4*)(A + (size_t)(m0 + lm + 32 * i) * lda + lc);
        rb[i] = *(const float4*)(B + (size_t)(n0 + lm + 32 * i) * ldb + lc);
    }
    for (int ci = 0; ci < NC; ci++) {
        if (ci > 0) __syncthreads();
#pragma unroll
        for (int i = 0; i < 4; i++) {
            int base = (lm + 32 * i) * B_STRIDE + (lc >> 1);
            float4 v = ra[i];
            __nv_bfloat162 h01 = __floats2bfloat162_rn(v.x, v.y);
            __nv_bfloat162 h23 = __floats2bfloat162_rn(v.z, v.w);
            __nv_bfloat162 l01 = __floats2bfloat162_rn(v.x - __bfloat162float(h01.x),
                                                       v.y - __bfloat162float(h01.y));
            __nv_bfloat162 l23 = __floats2bfloat162_rn(v.z - __bfloat162float(h23.x),
                                                       v.w - __bfloat162float(h23.y));
            *(uint2*)&sAh[base] = make_uint2(*(uint32_t*)&h01, *(uint32_t*)&h23);
            *(uint2*)&sAl[base] = make_uint2(*(uint32_t*)&l01, *(uint32_t*)&l23);
            v = rb[i];
            h01 = __floats2bfloat162_rn(v.x, v.y);
            h23 = __floats2bfloat162_rn(v.z, v.w);
            l01 = __floats2bfloat162_rn(v.x - __bfloat162float(h01.x),
                                        v.y - __bfloat162float(h01.y));
            l23 = __floats2bfloat162_rn(v.z - __bfloat162float(h23.x),
                                        v.w - __bfloat162float(h23.y));
            *(uint2*)&sBh[base] = make_uint2(*(uint32_t*)&h01, *(uint32_t*)&h23);
            *(uint2*)&sBl[base] = make_uint2(*(uint32_t*)&l01, *(uint32_t*)&l23);
        }
        __syncthreads();
        if (ci + 1 < NC) {
            int k0 = (ci + 1) * 32;
#pragma unroll
            for (int i = 0; i < 4; i++) {
                ra[i] = *(const float4*)(A + (size_t)(m0 + lm + 32 * i) * lda + k0 + lc);
                rb[i] = *(const float4*)(B + (size_t)(n0 + lm + 32 * i) * ldb + k0 + lc);
            }
        }
#pragma unroll
        for (int s = 0; s < 2; s++) {
            uint32_t ah[2][4], al[2][4], bh[8][2], bl[8][2];
#pragma unroll
            for (int mt = 0; mt < 2; mt++) {
                int base = (wm + mt * 16 + g) * B_STRIDE + s * 8 + tig;
                ah[mt][0] = sAh[base];
                ah[mt][1] = sAh[base + 8 * B_STRIDE];
                ah[mt][2] = sAh[base + 4];
                ah[mt][3] = sAh[base + 8 * B_STRIDE + 4];
                al[mt][0] = sAl[base];
                al[mt][1] = sAl[base + 8 * B_STRIDE];
                al[mt][2] = sAl[base + 4];
                al[mt][3] = sAl[base + 8 * B_STRIDE + 4];
            }
#pragma unroll
            for (int nt = 0; nt < 8; nt++) {
                int base = (wn + nt * 8 + g) * B_STRIDE + s * 8 + tig;
                bh[nt][0] = sBh[base];
                bh[nt][1] = sBh[base + 4];
                bl[nt][0] = sBl[base];
                bl[nt][1] = sBl[base + 4];
            }
#pragma unroll
            for (int mt = 0; mt < 2; mt++)
#pragma unroll
                for (int nt = 0; nt < 8; nt++) {
                    mma_bf16(acc[mt][nt], ah[mt], bh[nt]);
                    mma_bf16(acc[mt][nt], ah[mt], bl[nt]);
                    mma_bf16(acc[mt][nt], al[mt], bh[nt]);
                }
        }
    }
#pragma unroll
    for (int mt = 0; mt < 2; mt++) {
        int row = m0 + wm + mt * 16 + g;
#pragma unroll
        for (int nt = 0; nt < 8; nt++) {
            int col = n0 + wn + nt * 8 + 2 * tig;
            *(float2*)(C + (size_t)row * ldc + col) =
                make_float2(acc[mt][nt][0], acc[mt][nt][1]);
            *(float2*)(C + (size_t)(row + 8) * ldc + col) =
                make_float2(acc[mt][nt][2], acc[mt][nt][3]);
        }
    }
}

// ------------------------------------------------------------------
// im2col of x2 (k=3,s=1,pad=1) + patch inverse norms
// ------------------------------------------------------------------
__global__ void im2col_norm_kernel(const float* __restrict__ x2) {
    int p = blockIdx.x;
    int pi = p >> 6, pj = p & 63;
    int tid = threadIdx.x;
    float ss = 0.f;
    for (int k = tid; k < KPATCH; k += 256) {
        int c = k / 9, ki = k % 9;
        int ky = ki / 3, kx = ki % 3;
        int yy = pi - 1 + ky, xx = pj - 1 + kx;
        float v = 0.f;
        if (yy >= 0 && yy < H2N && xx >= 0 && xx < W2N)
            v = x2[(c * H2N + yy) * W2N + xx];
        g_A[p * KPATCH + k] = v;
        ss += v * v;
    }
    __shared__ float red[256];
    red[tid] = ss;
    __syncthreads();
    for (int s = 128; s > 0; s >>= 1) {
        if (tid < s) red[tid] += red[tid + s];
        __syncthreads();
    }
    if (tid == 0) {
        float n = sqrtf(red[0]);
        g_invn[p] = 1.f / fmaxf(n, 1e-4f);
    }
}

// ------------------------------------------------------------------
// mask patches (k=4,s=2,pad=1): mm[q] = (sum == 0) ? 1 : 0
// ------------------------------------------------------------------
__global__ void mask_patch_kernel(const float* __restrict__ mask) {
    int q = blockIdx.x * blockDim.x + threadIdx.x;
    if (q >= LP) return;
    int qi = q >> 6, qj = q & 63;
    float s = 0.f;
    for (int ky = 0; ky < 4; ky++)
        for (int kx = 0; kx < 4; kx++) {
            int yy = 2 * qi - 1 + ky, xx = 2 * qj - 1 + kx;
            if (yy >= 0 && yy < H1N && xx >= 0 && xx < W1N)
                s += mask[yy * W1N + xx];
        }
    g_mm[q] = (s == 0.f) ? 1.f : 0.f;
}

// ------------------------------------------------------------------
// masked softmax over q for each row p (in-place on g_S)
// ------------------------------------------------------------------
__global__ void __launch_bounds__(256) softmax_kernel(const float* __restrict__ mask_all) {
    int p = blockIdx.x;
    int tid = threadIdx.x;
    float map = mask_all[p];
    float* row = g_S + (size_t)p * LP;

    float v[16];
    float lmax = -1e30f;
#pragma unroll
    for (int i = 0; i < 16; i++) {
        int q = tid + i * 256;
        float x = row[q] * g_mm[q] * map;
        v[i] = x;
        lmax = fmaxf(lmax, x);
    }
    __shared__ float red[256];
    red[tid] = lmax;
    __syncthreads();
    for (int s = 128; s > 0; s >>= 1) {
        if (tid < s) red[tid] = fmaxf(red[tid], red[tid + s]);
        __syncthreads();
    }
    float gmax = red[0];
    __syncthreads();

    float lsum = 0.f;
#pragma unroll
    for (int i = 0; i < 16; i++) {
        float e = expf(SCALE_F * (v[i] - gmax));
        v[i] = e;
        lsum += e;
    }
    red[tid] = lsum;
    __syncthreads();
    for (int s = 128; s > 0; s >>= 1) {
        if (tid < s) red[tid] += red[tid + s];
        __syncthreads();
    }
    float inv = 1.f / red[0];
#pragma unroll
    for (int i = 0; i < 16; i++) {
        int q = tid + i * 256;
        row[q] = fmaxf(v[i] * inv * g_mm[q] * map, 1e-8f);
    }
}

// ------------------------------------------------------------------
// rawT[m][q] = x1 patch gather (k=4, s=2, pad=1), m = o*16 + ky*4 + kx
// ------------------------------------------------------------------
__global__ void fill_raw_kernel(const float* __restrict__ x1) {
    int q = blockIdx.x * blockDim.x + threadIdx.x;
    int m = blockIdx.y;
    int o = m >> 4, kk = m & 15;
    int ky = kk >> 2, kx = kk & 3;
    int qi = q >> 6, qj = q & 63;
    int yy = 2 * qi - 1 + ky, xx = 2 * qj - 1 + kx;
    float v = 0.f;
    if (yy >= 0 && yy < H1N && xx >= 0 && xx < W1N)
        v = x1[(o * H1N + yy) * W1N + xx];
    g_raw[(size_t)m * LP + q] = v;
}

// ------------------------------------------------------------------
// col2im gather: y[o,Y,X] = 0.25 * sum over <=4 entries of g_cols
// ------------------------------------------------------------------
__global__ void col2im_kernel(int b) {
    int idx = blockIdx.x * blockDim.x + threadIdx.x;
    int X = idx & 127;
    int Y = (idx >> 7) & 127;
    int o = idx >> 14;
    float acc = 0.f;
    int ky0 = (Y & 1) ? 0 : 1;
    int kx0 = (X & 1) ? 0 : 1;
#pragma unroll
    for (int t = 0; t < 2; t++) {
        int ky = ky0 + 2 * t;
        int i = (Y + 1 - ky) >> 1;
        if (i < 0 || i >= 64) continue;
#pragma unroll
        for (int u = 0; u < 2; u++) {
            int kx = kx0 + 2 * u;
            int j = (X + 1 - kx) >> 1;
            if (j < 0 || j >= 64) continue;
            acc += g_cols[(size_t)(o * 16 + ky * 4 + kx) * LP + i * 64 + j];
        }
    }
    g_y[(size_t)b * C1N * H1N * W1N + idx] = acc * 0.25f;
}

// ------------------------------------------------------------------
// final: 4 grouped dilated 3x3 convs (rates 1,2,4,8) + bias + relu
// ------------------------------------------------------------------
__global__ void __launch_bounds__(256) final_conv_kernel(
    const float* __restrict__ w, const float* __restrict__ bias, float* __restrict__ out)
{
    int tile = blockIdx.x;
    int g = blockIdx.y;
    int b = blockIdx.z;
    int r = 1 << g;  // rates 1,2,4,8
    int ty0 = (tile >> 3) * 16, tx0 = (tile & 7) * 16;
    int HW = 16 + 2 * r;
    __shared__ float yt[32 * 32];
    __shared__ float ws[144];
    int tid = threadIdx.x;
    int py = tid >> 4, px = tid & 15;

    float acc[16];
#pragma unroll
    for (int i = 0; i < 16; i++) acc[i] = 0.f;

    const float* yb = g_y + (size_t)b * C1N * H1N * W1N;
    for (int c = 0; c < C1N; c++) {
        for (int idx = tid; idx < HW * HW; idx += 256) {
            int iy = idx / HW, ix = idx % HW;
            int gy = ty0 - r + iy, gx = tx0 - r + ix;
            float v = 0.f;
            if (gy >= 0 && gy < H1N && gx >= 0 && gx < W1N)
                v = yb[(c * H1N + gy) * W1N + gx];
            yt[idx] = v;
        }
        if (tid < 144)
            ws[tid] = w[((g * 16 + tid / 9) * C1N + c) * 9 + tid % 9];
        __syncthreads();
#pragma unroll
        for (int ky = 0; ky < 3; ky++)
#pragma unroll
            for (int kx = 0; kx < 3; kx++) {
                float v = yt[(py + ky * r) * HW + px + kx * r];
#pragma unroll
                for (int oc = 0; oc < 16; oc++)
                    acc[oc] += v * ws[oc * 9 + ky * 3 + kx];
            }
        __syncthreads();
    }
    int Y = ty0 + py, X = tx0 + px;
#pragma unroll
    for (int oc = 0; oc < 16; oc++) {
        float o = acc[oc] + bias[g * 16 + oc];
        out[((size_t)(b * 64 + g * 16 + oc) * H1N + Y) * W1N + X] = fmaxf(o, 0.f);
    }
}

// ------------------------------------------------------------------
extern "C" void kernel_launch(void* const* d_in, const int* in_sizes, int n_in,
                              void* d_out, int out_size) {
    const float* x1       = (const float*)d_in[0];  // [4,128,128,128]
    const float* x2       = (const float*)d_in[1];  // [4,64,64,64]
    const float* mask     = (const float*)d_in[2];  // [4,1,128,128]
    const float* mask_all = (const float*)d_in[3];  // [4,1,64,64]
    const float* conv_w   = (const float*)d_in[4];  // [4,16,128,3,3]
    const float* conv_b   = (const float*)d_in[5];  // [4,16]
    float* out = (float*)d_out;

    for (int b = 0; b < BATCH; b++) {
        im2col_norm_kernel<<<LP, 256>>>(x2 + (size_t)b * C2N * H2N * W2N);
        mask_patch_kernel<<<LP / 256, 256>>>(mask + (size_t)b * H1N * W1N);
        gemm1_mma<<<dim3(32, 32), 256>>>();
        softmax_kernel<<<LP, 256>>>(mask_all + (size_t)b * LP);
        fill_raw_kernel<<<dim3(LP / 256, MRAW), 256>>>(x1 + (size_t)b * C1N * H1N * W1N);
        gemm2_mma<<<dim3(32, 16), 256>>>();
        col2im_kernel<<<(C1N * H1N * W1N) / 256, 256>>>(b);
    }
    final_conv_kernel<<<dim3(64, 4, 4), 256>>>(conv_w, conv_b, out);
}

// round 7
// speedup vs baseline: 2.3453x; 1.3297x over previous
#include <cuda_runtime.h>
#include <cuda_fp16.h>
#include <math.h>
#include <stdint.h>

#define BATCH 4
#define C1N 128
#define H1N 128
#define W1N 128
#define C2N 64
#define H2N 64
#define W2N 64
#define LP 4096          // H2*W2 positions / patches
#define KPATCH 576       // C2 * 3 * 3
#define MRAW 2048        // C1 * 4 * 4
#define SCALE_F 10.0f

// ---- scratch (device globals: allocation-free) ----
__device__ __half g_Ah[LP * KPATCH];        // im2col(x2) hi  [p][k]
__device__ __half g_Al[LP * KPATCH];        // im2col(x2) lo
__device__ float  g_invn[LP];
__device__ float  g_mm[LP];
__device__ float  g_S[(size_t)LP * LP];     // fp32 scores  [p][q]
__device__ __half g_P[(size_t)LP * LP];     // softmax out (fp16)  [p][q]
__device__ __half g_rawh[(size_t)MRAW * LP]; // rawT hi [m][q]
__device__ __half g_rawl[(size_t)MRAW * LP]; // rawT lo
__device__ float  g_cols[(size_t)MRAW * LP]; // GEMM2 out [m][pos]
__device__ float  g_y[(size_t)BATCH * C1N * H1N * W1N];

// ==================================================================
// mma.sync fp16 (base PTX, compiles at compute_103)
// ==================================================================
__device__ __forceinline__ void mma_f16(float d[4], const uint32_t a[4], const uint32_t b[2]) {
    asm volatile(
        "mma.sync.aligned.m16n8k16.row.col.f32.f16.f16.f32 "
        "{%0,%1,%2,%3},{%4,%5,%6,%7},{%8,%9},{%0,%1,%2,%3};"
        : "+f"(d[0]), "+f"(d[1]), "+f"(d[2]), "+f"(d[3])
        : "r"(a[0]), "r"(a[1]), "r"(a[2]), "r"(a[3]), "r"(b[0]), "r"(b[1]));
}

#define SSTR 20   // smem row stride in u32 words (16 data + 4 pad: conflict-free)

// ==================================================================
// GEMM1: S[p][q] = <A_p, A_q> * invn[q]; both operands fp16 2-term
// split, 3 MMA terms. M=N=4096, K=576, BK=32, 8 warps, 128x128 tile.
// ==================================================================
__global__ void __launch_bounds__(256) gemm1_mma() {
    __shared__ uint32_t sAh[128 * SSTR], sAl[128 * SSTR];
    __shared__ uint32_t sBh[128 * SSTR], sBl[128 * SSTR];
    const int K = KPATCH;
    int t = threadIdx.x;
    int m0 = blockIdx.y * 128, n0 = blockIdx.x * 128;
    int wid = t >> 5, lane = t & 31;
    int wm = (wid >> 1) * 32, wn = (wid & 1) * 64;
    int g = lane >> 2, tig = lane & 3;

    float acc[2][8][4] = {};

    int lm = t >> 1;              // row 0..127
    int lw = (t & 1) * 8;         // u32-word offset within 16-word row
    int sbase = lm * SSTR + lw;
    const __half* pAh = g_Ah + (size_t)(m0 + lm) * K + lw * 2;
    const __half* pAl = g_Al + (size_t)(m0 + lm) * K + lw * 2;
    const __half* pBh = g_Ah + (size_t)(n0 + lm) * K + lw * 2;
    const __half* pBl = g_Al + (size_t)(n0 + lm) * K + lw * 2;

    const int NC = K / 32;
    uint4 vah = *(const uint4*)pAh;
    uint4 vah2 = *(const uint4*)(pAh + 8);
    uint4 val_ = *(const uint4*)pAl;
    uint4 val2 = *(const uint4*)(pAl + 8);
    uint4 vbh = *(const uint4*)pBh;
    uint4 vbh2 = *(const uint4*)(pBh + 8);
    uint4 vbl = *(const uint4*)pBl;
    uint4 vbl2 = *(const uint4*)(pBl + 8);

    for (int ci = 0; ci < NC; ci++) {
        if (ci > 0) __syncthreads();
        *(uint4*)&sAh[sbase] = vah;  *(uint4*)&sAh[sbase + 4] = vah2;
        *(uint4*)&sAl[sbase] = val_; *(uint4*)&sAl[sbase + 4] = val2;
        *(uint4*)&sBh[sbase] = vbh;  *(uint4*)&sBh[sbase + 4] = vbh2;
        *(uint4*)&sBl[sbase] = vbl;  *(uint4*)&sBl[sbase + 4] = vbl2;
        __syncthreads();
        if (ci + 1 < NC) {
            int k0 = (ci + 1) * 32;
            vah = *(const uint4*)(pAh + k0);
            vah2 = *(const uint4*)(pAh + k0 + 8);
            val_ = *(const uint4*)(pAl + k0);
            val2 = *(const uint4*)(pAl + k0 + 8);
            vbh = *(const uint4*)(pBh + k0);
            vbh2 = *(const uint4*)(pBh + k0 + 8);
            vbl = *(const uint4*)(pBl + k0);
            vbl2 = *(const uint4*)(pBl + k0 + 8);
        }
#pragma unroll
        for (int s = 0; s < 2; s++) {
            uint32_t ah[2][4], al[2][4], bh[8][2], bl[8][2];
#pragma unroll
            for (int mt = 0; mt < 2; mt++) {
                int base = (wm + mt * 16 + g) * SSTR + s * 8 + tig;
                ah[mt][0] = sAh[base];
                ah[mt][1] = sAh[base + 8 * SSTR];
                ah[mt][2] = sAh[base + 4];
                ah[mt][3] = sAh[base + 8 * SSTR + 4];
                al[mt][0] = sAl[base];
                al[mt][1] = sAl[base + 8 * SSTR];
                al[mt][2] = sAl[base + 4];
                al[mt][3] = sAl[base + 8 * SSTR + 4];
            }
#pragma unroll
            for (int nt = 0; nt < 8; nt++) {
                int base = (wn + nt * 8 + g) * SSTR + s * 8 + tig;
                bh[nt][0] = sBh[base];
                bh[nt][1] = sBh[base + 4];
                bl[nt][0] = sBl[base];
                bl[nt][1] = sBl[base + 4];
            }
#pragma unroll
            for (int mt = 0; mt < 2; mt++)
#pragma unroll
                for (int nt = 0; nt < 8; nt++) {
                    mma_f16(acc[mt][nt], ah[mt], bh[nt]);
                    mma_f16(acc[mt][nt], ah[mt], bl[nt]);
                    mma_f16(acc[mt][nt], al[mt], bh[nt]);
                }
        }
    }
    // epilogue: scale by invn[col], write fp32 scores
#pragma unroll
    for (int mt = 0; mt < 2; mt++) {
        int row = m0 + wm + mt * 16 + g;
#pragma unroll
        for (int nt = 0; nt < 8; nt++) {
            int col = n0 + wn + nt * 8 + 2 * tig;
            float s0 = __ldg(&g_invn[col]);
            float s1 = __ldg(&g_invn[col + 1]);
            *(float2*)(g_S + (size_t)row * LP + col) =
                make_float2(acc[mt][nt][0] * s0, acc[mt][nt][1] * s1);
            *(float2*)(g_S + (size_t)(row + 8) * LP + col) =
                make_float2(acc[mt][nt][2] * s0, acc[mt][nt][3] * s1);
        }
    }
}

// ==================================================================
// GEMM2: cols[m][p] = sum_q raw[m][q] * P[p][q]
// A = raw fp16 2-term split (2 MMA terms), B = P single fp16.
// M=2048, N=4096, K=4096, BK=32, 8 warps, 128x128 tile.
// ==================================================================
__global__ void __launch_bounds__(256) gemm2_mma() {
    __shared__ uint32_t sAh[128 * SSTR], sAl[128 * SSTR];
    __shared__ uint32_t sB[128 * SSTR];
    int t = threadIdx.x;
    int m0 = blockIdx.y * 128, n0 = blockIdx.x * 128;
    int wid = t >> 5, lane = t & 31;
    int wm = (wid >> 1) * 32, wn = (wid & 1) * 64;
    int g = lane >> 2, tig = lane & 3;

    float acc[2][8][4] = {};

    int lm = t >> 1;
    int lw = (t & 1) * 8;
    int sbase = lm * SSTR + lw;
    const __half* pAh = g_rawh + (size_t)(m0 + lm) * LP + lw * 2;
    const __half* pAl = g_rawl + (size_t)(m0 + lm) * LP + lw * 2;
    const __half* pB  = g_P    + (size_t)(n0 + lm) * LP + lw * 2;

    const int NC = LP / 32;
    uint4 vah = *(const uint4*)pAh;
    uint4 vah2 = *(const uint4*)(pAh + 8);
    uint4 val_ = *(const uint4*)pAl;
    uint4 val2 = *(const uint4*)(pAl + 8);
    uint4 vb = *(const uint4*)pB;
    uint4 vb2 = *(const uint4*)(pB + 8);

    for (int ci = 0; ci < NC; ci++) {
        if (ci > 0) __syncthreads();
        *(uint4*)&sAh[sbase] = vah;  *(uint4*)&sAh[sbase + 4] = vah2;
        *(uint4*)&sAl[sbase] = val_; *(uint4*)&sAl[sbase + 4] = val2;
        *(uint4*)&sB[sbase]  = vb;   *(uint4*)&sB[sbase + 4]  = vb2;
        __syncthreads();
        if (ci + 1 < NC) {
            int k0 = (ci + 1) * 32;
            vah = *(const uint4*)(pAh + k0);
            vah2 = *(const uint4*)(pAh + k0 + 8);
            val_ = *(const uint4*)(pAl + k0);
            val2 = *(const uint4*)(pAl + k0 + 8);
            vb = *(const uint4*)(pB + k0);
            vb2 = *(const uint4*)(pB + k0 + 8);
        }
#pragma unroll
        for (int s = 0; s < 2; s++) {
            uint32_t ah[2][4], al[2][4], b[8][2];
#pragma unroll
            for (int mt = 0; mt < 2; mt++) {
                int base = (wm + mt * 16 + g) * SSTR + s * 8 + tig;
                ah[mt][0] = sAh[base];
                ah[mt][1] = sAh[base + 8 * SSTR];
                ah[mt][2] = sAh[base + 4];
                ah[mt][3] = sAh[base + 8 * SSTR + 4];
                al[mt][0] = sAl[base];
                al[mt][1] = sAl[base + 8 * SSTR];
                al[mt][2] = sAl[base + 4];
                al[mt][3] = sAl[base + 8 * SSTR + 4];
            }
#pragma unroll
            for (int nt = 0; nt < 8; nt++) {
                int base = (wn + nt * 8 + g) * SSTR + s * 8 + tig;
                b[nt][0] = sB[base];
                b[nt][1] = sB[base + 4];
            }
#pragma unroll
            for (int mt = 0; mt < 2; mt++)
#pragma unroll
                for (int nt = 0; nt < 8; nt++) {
                    mma_f16(acc[mt][nt], ah[mt], b[nt]);
                    mma_f16(acc[mt][nt], al[mt], b[nt]);
                }
        }
    }
#pragma unroll
    for (int mt = 0; mt < 2; mt++) {
        int row = m0 + wm + mt * 16 + g;
#pragma unroll
        for (int nt = 0; nt < 8; nt++) {
            int col = n0 + wn + nt * 8 + 2 * tig;
            *(float2*)(g_cols + (size_t)row * LP + col) =
                make_float2(acc[mt][nt][0], acc[mt][nt][1]);
            *(float2*)(g_cols + (size_t)(row + 8) * LP + col) =
                make_float2(acc[mt][nt][2], acc[mt][nt][3]);
        }
    }
}

// ------------------------------------------------------------------
// im2col of x2 (k=3,s=1,pad=1) -> fp16 hi/lo split + inverse norms
// ------------------------------------------------------------------
__global__ void im2col_norm_kernel(const float* __restrict__ x2) {
    int p = blockIdx.x;
    int pi = p >> 6, pj = p & 63;
    int tid = threadIdx.x;
    float ss = 0.f;
    for (int k = tid; k < KPATCH; k += 256) {
        int c = k / 9, ki = k % 9;
        int ky = ki / 3, kx = ki % 3;
        int yy = pi - 1 + ky, xx = pj - 1 + kx;
        float v = 0.f;
        if (yy >= 0 && yy < H2N && xx >= 0 && xx < W2N)
            v = x2[(c * H2N + yy) * W2N + xx];
        __half h = __float2half_rn(v);
        g_Ah[p * KPATCH + k] = h;
        g_Al[p * KPATCH + k] = __float2half_rn(v - __half2float(h));
        ss += v * v;
    }
    __shared__ float red[256];
    red[tid] = ss;
    __syncthreads();
    for (int s = 128; s > 0; s >>= 1) {
        if (tid < s) red[tid] += red[tid + s];
        __syncthreads();
    }
    if (tid == 0) {
        float n = sqrtf(red[0]);
        g_invn[p] = 1.f / fmaxf(n, 1e-4f);
    }
}

// ------------------------------------------------------------------
// mask patches (k=4,s=2,pad=1): mm[q] = (sum == 0) ? 1 : 0
// ------------------------------------------------------------------
__global__ void mask_patch_kernel(const float* __restrict__ mask) {
    int q = blockIdx.x * blockDim.x + threadIdx.x;
    if (q >= LP) return;
    int qi = q >> 6, qj = q & 63;
    float s = 0.f;
    for (int ky = 0; ky < 4; ky++)
        for (int kx = 0; kx < 4; kx++) {
            int yy = 2 * qi - 1 + ky, xx = 2 * qj - 1 + kx;
            if (yy >= 0 && yy < H1N && xx >= 0 && xx < W1N)
                s += mask[yy * W1N + xx];
        }
    g_mm[q] = (s == 0.f) ? 1.f : 0.f;
}

// ------------------------------------------------------------------
// masked softmax over q for each row p; writes fp16 P
// ------------------------------------------------------------------
__global__ void __launch_bounds__(256) softmax_kernel(const float* __restrict__ mask_all) {
    int p = blockIdx.x;
    int tid = threadIdx.x;
    float map = mask_all[p];
    const float* row = g_S + (size_t)p * LP;
    __half* prow = g_P + (size_t)p * LP;

    float v[16];
    float lmax = -1e30f;
#pragma unroll
    for (int i = 0; i < 16; i++) {
        int q = tid + i * 256;
        float x = row[q] * g_mm[q] * map;
        v[i] = x;
        lmax = fmaxf(lmax, x);
    }
    __shared__ float red[256];
    red[tid] = lmax;
    __syncthreads();
    for (int s = 128; s > 0; s >>= 1) {
        if (tid < s) red[tid] = fmaxf(red[tid], red[tid + s]);
        __syncthreads();
    }
    float gmax = red[0];
    __syncthreads();

    float lsum = 0.f;
#pragma unroll
    for (int i = 0; i < 16; i++) {
        float e = expf(SCALE_F * (v[i] - gmax));
        v[i] = e;
        lsum += e;
    }
    red[tid] = lsum;
    __syncthreads();
    for (int s = 128; s > 0; s >>= 1) {
        if (tid < s) red[tid] += red[tid + s];
        __syncthreads();
    }
    float inv = 1.f / red[0];
#pragma unroll
    for (int i = 0; i < 16; i++) {
        int q = tid + i * 256;
        float pv = fmaxf(v[i] * inv * g_mm[q] * map, 1e-8f);
        prow[q] = __float2half_rn(pv);
    }
}

// ------------------------------------------------------------------
// rawT[m][q] -> fp16 hi/lo split (k=4, s=2, pad=1), m = o*16+ky*4+kx
// ------------------------------------------------------------------
__global__ void fill_raw_kernel(const float* __restrict__ x1) {
    int q = blockIdx.x * blockDim.x + threadIdx.x;
    int m = blockIdx.y;
    int o = m >> 4, kk = m & 15;
    int ky = kk >> 2, kx = kk & 3;
    int qi = q >> 6, qj = q & 63;
    int yy = 2 * qi - 1 + ky, xx = 2 * qj - 1 + kx;
    float v = 0.f;
    if (yy >= 0 && yy < H1N && xx >= 0 && xx < W1N)
        v = x1[(o * H1N + yy) * W1N + xx];
    __half h = __float2half_rn(v);
    g_rawh[(size_t)m * LP + q] = h;
    g_rawl[(size_t)m * LP + q] = __float2half_rn(v - __half2float(h));
}

// ------------------------------------------------------------------
// col2im gather: y[o,Y,X] = 0.25 * sum over <=4 entries of g_cols
// ------------------------------------------------------------------
__global__ void col2im_kernel(int b) {
    int idx = blockIdx.x * blockDim.x + threadIdx.x;
    int X = idx & 127;
    int Y = (idx >> 7) & 127;
    int o = idx >> 14;
    float acc = 0.f;
    int ky0 = (Y & 1) ? 0 : 1;
    int kx0 = (X & 1) ? 0 : 1;
#pragma unroll
    for (int t = 0; t < 2; t++) {
        int ky = ky0 + 2 * t;
        int i = (Y + 1 - ky) >> 1;
        if (i < 0 || i >= 64) continue;
#pragma unroll
        for (int u = 0; u < 2; u++) {
            int kx = kx0 + 2 * u;
            int j = (X + 1 - kx) >> 1;
            if (j < 0 || j >= 64) continue;
            acc += g_cols[(size_t)(o * 16 + ky * 4 + kx) * LP + i * 64 + j];
        }
    }
    g_y[(size_t)b * C1N * H1N * W1N + idx] = acc * 0.25f;
}

// ------------------------------------------------------------------
// final: 4 grouped dilated 3x3 convs (rates 1,2,4,8) + bias + relu
// ------------------------------------------------------------------
__global__ void __launch_bounds__(256) final_conv_kernel(
    const float* __restrict__ w, const float* __restrict__ bias, float* __restrict__ out)
{
    int tile = blockIdx.x;
    int g = blockIdx.y;
    int b = blockIdx.z;
    int r = 1 << g;  // rates 1,2,4,8
    int ty0 = (tile >> 3) * 16, tx0 = (tile & 7) * 16;
    int HW = 16 + 2 * r;
    __shared__ float yt[32 * 32];
    __shared__ float ws[144];
    int tid = threadIdx.x;
    int py = tid >> 4, px = tid & 15;

    float acc[16];
#pragma unroll
    for (int i = 0; i < 16; i++) acc[i] = 0.f;

    const float* yb = g_y + (size_t)b * C1N * H1N * W1N;
    for (int c = 0; c < C1N; c++) {
        for (int idx = tid; idx < HW * HW; idx += 256) {
            int iy = idx / HW, ix = idx % HW;
            int gy = ty0 - r + iy, gx = tx0 - r + ix;
            float v = 0.f;
            if (gy >= 0 && gy < H1N && gx >= 0 && gx < W1N)
                v = yb[(c * H1N + gy) * W1N + gx];
            yt[idx] = v;
        }
        if (tid < 144)
            ws[tid] = w[((g * 16 + tid / 9) * C1N + c) * 9 + tid % 9];
        __syncthreads();
#pragma unroll
        for (int ky = 0; ky < 3; ky++)
#pragma unroll
            for (int kx = 0; kx < 3; kx++) {
                float v = yt[(py + ky * r) * HW + px + kx * r];
#pragma unroll
                for (int oc = 0; oc < 16; oc++)
                    acc[oc] += v * ws[oc * 9 + ky * 3 + kx];
            }
        __syncthreads();
    }
    int Y = ty0 + py, X = tx0 + px;
#pragma unroll
    for (int oc = 0; oc < 16; oc++) {
        float o = acc[oc] + bias[g * 16 + oc];
        out[((size_t)(b * 64 + g * 16 + oc) * H1N + Y) * W1N + X] = fmaxf(o, 0.f);
    }
}

// ------------------------------------------------------------------
extern "C" void kernel_launch(void* const* d_in, const int* in_sizes, int n_in,
                              void* d_out, int out_size) {
    const float* x1       = (const float*)d_in[0];  // [4,128,128,128]
    const float* x2       = (const float*)d_in[1];  // [4,64,64,64]
    const float* mask     = (const float*)d_in[2];  // [4,1,128,128]
    const float* mask_all = (const float*)d_in[3];  // [4,1,64,64]
    const float* conv_w   = (const float*)d_in[4];  // [4,16,128,3,3]
    const float* conv_b   = (const float*)d_in[5];  // [4,16]
    float* out = (float*)d_out;

    for (int b = 0; b < BATCH; b++) {
        im2col_norm_kernel<<<LP, 256>>>(x2 + (size_t)b * C2N * H2N * W2N);
        mask_patch_kernel<<<LP / 256, 256>>>(mask + (size_t)b * H1N * W1N);
        gemm1_mma<<<dim3(32, 32), 256>>>();
        softmax_kernel<<<LP, 256>>>(mask_all + (size_t)b * LP);
        fill_raw_kernel<<<dim3(LP / 256, MRAW), 256>>>(x1 + (size_t)b * C1N * H1N * W1N);
        gemm2_mma<<<dim3(32, 16), 256>>>();
        col2im_kernel<<<(C1N * H1N * W1N) / 256, 256>>>(b);
    }
    final_conv_kernel<<<dim3(64, 4, 4), 256>>>(conv_w, conv_b, out);
}

// round 8
// speedup vs baseline: 3.1271x; 1.3333x over previous
#include <cuda_runtime.h>
#include <cuda_fp16.h>
#include <math.h>
#include <stdint.h>

#define BATCH 4
#define C1N 128
#define H1N 128
#define W1N 128
#define C2N 64
#define H2N 64
#define W2N 64
#define LP 4096          // H2*W2 positions / patches
#define KPATCH 576       // C2 * 3 * 3
#define MRAW 2048        // C1 * 4 * 4
#define SCALE_F 10.0f

// ---- scratch (device globals: allocation-free) ----
__device__ __half g_Ah[LP * KPATCH];        // im2col(x2) hi  [p][k]
__device__ __half g_Al[LP * KPATCH];        // im2col(x2) lo
__device__ float  g_invn[LP];
__device__ float  g_mm[LP];
__device__ float  g_S[(size_t)LP * LP];     // fp32 scores  [p][q]
__device__ __half g_P[(size_t)LP * LP];     // softmax out (fp16)  [p][q]
__device__ __half g_rawh[(size_t)MRAW * LP]; // rawT fp16 [m][q]
__device__ float  g_cols[(size_t)MRAW * LP]; // GEMM2 out [m][pos]
__device__ float  g_y[(size_t)BATCH * C1N * H1N * W1N];

// ==================================================================
// mma.sync fp16 + ldmatrix (base PTX, compiles at compute_103)
// ==================================================================
__device__ __forceinline__ void mma_f16(float d[4], const uint32_t a[4], const uint32_t b[2]) {
    asm volatile(
        "mma.sync.aligned.m16n8k16.row.col.f32.f16.f16.f32 "
        "{%0,%1,%2,%3},{%4,%5,%6,%7},{%8,%9},{%0,%1,%2,%3};"
        : "+f"(d[0]), "+f"(d[1]), "+f"(d[2]), "+f"(d[3])
        : "r"(a[0]), "r"(a[1]), "r"(a[2]), "r"(a[3]), "r"(b[0]), "r"(b[1]));
}
#define LDSM_X4(R, addr) \
    asm volatile("ldmatrix.sync.aligned.m8n8.x4.shared.b16 {%0,%1,%2,%3}, [%4];" \
        : "=r"((R)[0]), "=r"((R)[1]), "=r"((R)[2]), "=r"((R)[3]) : "r"(addr))

__device__ __forceinline__ uint32_t smem_u32(const void* p) {
    uint32_t a;
    asm("{ .reg .u64 t; cvta.to.shared.u64 t, %1; cvt.u32.u64 %0, t; }" : "=r"(a) : "l"(p));
    return a;
}

#define SSTR 20   // smem row stride in u32 words (16 data + 4 pad)
// ldmatrix bank check: row starts at bank (20*r)%32 -> 8 consecutive rows
// cover all 32 banks exactly once with their 16B reads: conflict-free.

// ==================================================================
// GEMM1: S[p][q] = <A_p, A_q> * invn[q]; both operands fp16 2-term
// split, 3 MMA terms. M=N=4096, K=576, BK=32, 8 warps, 128x128 tile.
// ==================================================================
__global__ void __launch_bounds__(256) gemm1_mma() {
    __shared__ uint32_t sAh[128 * SSTR], sAl[128 * SSTR];
    __shared__ uint32_t sBh[128 * SSTR], sBl[128 * SSTR];
    const int K = KPATCH;
    int t = threadIdx.x;
    int m0 = blockIdx.y * 128, n0 = blockIdx.x * 128;
    int wid = t >> 5, lane = t & 31;
    int wm = (wid >> 1) * 32, wn = (wid & 1) * 64;
    int g = lane >> 2, tig = lane & 3;

    float acc[2][8][4] = {};

    int lm = t >> 1;              // row 0..127
    int lw = (t & 1) * 8;         // u32-word offset within 16-word row
    int sbase = lm * SSTR + lw;
    const __half* pAh = g_Ah + (size_t)(m0 + lm) * K + lw * 2;
    const __half* pAl = g_Al + (size_t)(m0 + lm) * K + lw * 2;
    const __half* pBh = g_Ah + (size_t)(n0 + lm) * K + lw * 2;
    const __half* pBl = g_Al + (size_t)(n0 + lm) * K + lw * 2;

    // ldmatrix per-lane source rows/column-halves
    int rowA = lane & 15;
    int koffA = ((lane >> 4) & 1) * 4;      // lanes 16-31: k-halves 8-15
    int rowB = (lane & 7) + ((lane & 16) >> 1);
    int koffB = ((lane & 8) >> 1);          // lanes 8-15,24-31: k-halves 8-15
    uint32_t aWh = smem_u32(sAh) + 4 * ((wm + rowA) * SSTR + koffA);
    uint32_t aWl = smem_u32(sAl) + 4 * ((wm + rowA) * SSTR + koffA);
    uint32_t bWh = smem_u32(sBh) + 4 * ((wn + rowB) * SSTR + koffB);
    uint32_t bWl = smem_u32(sBl) + 4 * ((wn + rowB) * SSTR + koffB);

    const int NC = K / 32;
    uint4 vah = *(const uint4*)pAh;
    uint4 vah2 = *(const uint4*)(pAh + 8);
    uint4 val_ = *(const uint4*)pAl;
    uint4 val2 = *(const uint4*)(pAl + 8);
    uint4 vbh = *(const uint4*)pBh;
    uint4 vbh2 = *(const uint4*)(pBh + 8);
    uint4 vbl = *(const uint4*)pBl;
    uint4 vbl2 = *(const uint4*)(pBl + 8);

    for (int ci = 0; ci < NC; ci++) {
        if (ci > 0) __syncthreads();
        *(uint4*)&sAh[sbase] = vah;  *(uint4*)&sAh[sbase + 4] = vah2;
        *(uint4*)&sAl[sbase] = val_; *(uint4*)&sAl[sbase + 4] = val2;
        *(uint4*)&sBh[sbase] = vbh;  *(uint4*)&sBh[sbase + 4] = vbh2;
        *(uint4*)&sBl[sbase] = vbl;  *(uint4*)&sBl[sbase + 4] = vbl2;
        __syncthreads();
        if (ci + 1 < NC) {
            int k0 = (ci + 1) * 32;
            vah = *(const uint4*)(pAh + k0);
            vah2 = *(const uint4*)(pAh + k0 + 8);
            val_ = *(const uint4*)(pAl + k0);
            val2 = *(const uint4*)(pAl + k0 + 8);
            vbh = *(const uint4*)(pBh + k0);
            vbh2 = *(const uint4*)(pBh + k0 + 8);
            vbl = *(const uint4*)(pBl + k0);
            vbl2 = *(const uint4*)(pBl + k0 + 8);
        }
#pragma unroll
        for (int s = 0; s < 2; s++) {
            uint32_t ah[2][4], al[2][4], bh[8][2], bl[8][2];
#pragma unroll
            for (int mt = 0; mt < 2; mt++) {
                uint32_t off = (uint32_t)(mt * 16 * SSTR + s * 8) * 4;
                LDSM_X4(ah[mt], aWh + off);
                LDSM_X4(al[mt], aWl + off);
            }
#pragma unroll
            for (int ntp = 0; ntp < 4; ntp++) {
                uint32_t off = (uint32_t)(ntp * 16 * SSTR + s * 8) * 4;
                LDSM_X4(&bh[2 * ntp][0], bWh + off);
                LDSM_X4(&bl[2 * ntp][0], bWl + off);
            }
#pragma unroll
            for (int mt = 0; mt < 2; mt++)
#pragma unroll
                for (int nt = 0; nt < 8; nt++) {
                    mma_f16(acc[mt][nt], ah[mt], bh[nt]);
                    mma_f16(acc[mt][nt], ah[mt], bl[nt]);
                    mma_f16(acc[mt][nt], al[mt], bh[nt]);
                }
        }
    }
    // epilogue: scale by invn[col], write fp32 scores
#pragma unroll
    for (int mt = 0; mt < 2; mt++) {
        int row = m0 + wm + mt * 16 + g;
#pragma unroll
        for (int nt = 0; nt < 8; nt++) {
            int col = n0 + wn + nt * 8 + 2 * tig;
            float s0 = __ldg(&g_invn[col]);
            float s1 = __ldg(&g_invn[col + 1]);
            *(float2*)(g_S + (size_t)row * LP + col) =
                make_float2(acc[mt][nt][0] * s0, acc[mt][nt][1] * s1);
            *(float2*)(g_S + (size_t)(row + 8) * LP + col) =
                make_float2(acc[mt][nt][2] * s0, acc[mt][nt][3] * s1);
        }
    }
}

// ==================================================================
// GEMM2: cols[m][p] = sum_q raw[m][q] * P[p][q]
// A = raw single fp16, B = P single fp16 (1 MMA term).
// M=2048, N=4096, K=4096, BK=32, 8 warps, 128x128 tile.
// ==================================================================
__global__ void __launch_bounds__(256) gemm2_mma() {
    __shared__ uint32_t sA[128 * SSTR];
    __shared__ uint32_t sB[128 * SSTR];
    int t = threadIdx.x;
    int m0 = blockIdx.y * 128, n0 = blockIdx.x * 128;
    int wid = t >> 5, lane = t & 31;
    int wm = (wid >> 1) * 32, wn = (wid & 1) * 64;
    int g = lane >> 2, tig = lane & 3;

    float acc[2][8][4] = {};

    int lm = t >> 1;
    int lw = (t & 1) * 8;
    int sbase = lm * SSTR + lw;
    const __half* pA = g_rawh + (size_t)(m0 + lm) * LP + lw * 2;
    const __half* pB = g_P    + (size_t)(n0 + lm) * LP + lw * 2;

    int rowA = lane & 15;
    int koffA = ((lane >> 4) & 1) * 4;
    int rowB = (lane & 7) + ((lane & 16) >> 1);
    int koffB = ((lane & 8) >> 1);
    uint32_t aW = smem_u32(sA) + 4 * ((wm + rowA) * SSTR + koffA);
    uint32_t bW = smem_u32(sB) + 4 * ((wn + rowB) * SSTR + koffB);

    const int NC = LP / 32;
    uint4 va = *(const uint4*)pA;
    uint4 va2 = *(const uint4*)(pA + 8);
    uint4 vb = *(const uint4*)pB;
    uint4 vb2 = *(const uint4*)(pB + 8);

    for (int ci = 0; ci < NC; ci++) {
        if (ci > 0) __syncthreads();
        *(uint4*)&sA[sbase] = va;  *(uint4*)&sA[sbase + 4] = va2;
        *(uint4*)&sB[sbase] = vb;  *(uint4*)&sB[sbase + 4] = vb2;
        __syncthreads();
        if (ci + 1 < NC) {
            int k0 = (ci + 1) * 32;
            va = *(const uint4*)(pA + k0);
            va2 = *(const uint4*)(pA + k0 + 8);
            vb = *(const uint4*)(pB + k0);
            vb2 = *(const uint4*)(pB + k0 + 8);
        }
#pragma unroll
        for (int s = 0; s < 2; s++) {
            uint32_t a[2][4], b[8][2];
#pragma unroll
            for (int mt = 0; mt < 2; mt++) {
                uint32_t off = (uint32_t)(mt * 16 * SSTR + s * 8) * 4;
                LDSM_X4(a[mt], aW + off);
            }
#pragma unroll
            for (int ntp = 0; ntp < 4; ntp++) {
                uint32_t off = (uint32_t)(ntp * 16 * SSTR + s * 8) * 4;
                LDSM_X4(&b[2 * ntp][0], bW + off);
            }
#pragma unroll
            for (int mt = 0; mt < 2; mt++)
#pragma unroll
                for (int nt = 0; nt < 8; nt++)
                    mma_f16(acc[mt][nt], a[mt], b[nt]);
        }
    }
#pragma unroll
    for (int mt = 0; mt < 2; mt++) {
        int row = m0 + wm + mt * 16 + g;
#pragma unroll
        for (int nt = 0; nt < 8; nt++) {
            int col = n0 + wn + nt * 8 + 2 * tig;
            *(float2*)(g_cols + (size_t)row * LP + col) =
                make_float2(acc[mt][nt][0], acc[mt][nt][1]);
            *(float2*)(g_cols + (size_t)(row + 8) * LP + col) =
                make_float2(acc[mt][nt][2], acc[mt][nt][3]);
        }
    }
}

// ------------------------------------------------------------------
// im2col of x2 (k=3,s=1,pad=1) -> fp16 hi/lo split + inverse norms
// ------------------------------------------------------------------
__global__ void im2col_norm_kernel(const float* __restrict__ x2) {
    int p = blockIdx.x;
    int pi = p >> 6, pj = p & 63;
    int tid = threadIdx.x;
    float ss = 0.f;
    for (int k = tid; k < KPATCH; k += 256) {
        int c = k / 9, ki = k % 9;
        int ky = ki / 3, kx = ki % 3;
        int yy = pi - 1 + ky, xx = pj - 1 + kx;
        float v = 0.f;
        if (yy >= 0 && yy < H2N && xx >= 0 && xx < W2N)
            v = x2[(c * H2N + yy) * W2N + xx];
        __half h = __float2half_rn(v);
        g_Ah[p * KPATCH + k] = h;
        g_Al[p * KPATCH + k] = __float2half_rn(v - __half2float(h));
        ss += v * v;
    }
    __shared__ float red[256];
    red[tid] = ss;
    __syncthreads();
    for (int s = 128; s > 0; s >>= 1) {
        if (tid < s) red[tid] += red[tid + s];
        __syncthreads();
    }
    if (tid == 0) {
        float n = sqrtf(red[0]);
        g_invn[p] = 1.f / fmaxf(n, 1e-4f);
    }
}

// ------------------------------------------------------------------
// mask patches (k=4,s=2,pad=1): mm[q] = (sum == 0) ? 1 : 0
// ------------------------------------------------------------------
__global__ void mask_patch_kernel(const float* __restrict__ mask) {
    int q = blockIdx.x * blockDim.x + threadIdx.x;
    if (q >= LP) return;
    int qi = q >> 6, qj = q & 63;
    float s = 0.f;
    for (int ky = 0; ky < 4; ky++)
        for (int kx = 0; kx < 4; kx++) {
            int yy = 2 * qi - 1 + ky, xx = 2 * qj - 1 + kx;
            if (yy >= 0 && yy < H1N && xx >= 0 && xx < W1N)
                s += mask[yy * W1N + xx];
        }
    g_mm[q] = (s == 0.f) ? 1.f : 0.f;
}

// ------------------------------------------------------------------
// masked softmax over q for each row p; writes fp16 P
// ------------------------------------------------------------------
__global__ void __launch_bounds__(256) softmax_kernel(const float* __restrict__ mask_all) {
    int p = blockIdx.x;
    int tid = threadIdx.x;
    float map = mask_all[p];
    const float* row = g_S + (size_t)p * LP;
    __half* prow = g_P + (size_t)p * LP;

    float v[16];
    float lmax = -1e30f;
#pragma unroll
    for (int i = 0; i < 16; i++) {
        int q = tid + i * 256;
        float x = row[q] * g_mm[q] * map;
        v[i] = x;
        lmax = fmaxf(lmax, x);
    }
    __shared__ float red[256];
    red[tid] = lmax;
    __syncthreads();
    for (int s = 128; s > 0; s >>= 1) {
        if (tid < s) red[tid] = fmaxf(red[tid], red[tid + s]);
        __syncthreads();
    }
    float gmax = red[0];
    __syncthreads();

    float lsum = 0.f;
#pragma unroll
    for (int i = 0; i < 16; i++) {
        float e = expf(SCALE_F * (v[i] - gmax));
        v[i] = e;
        lsum += e;
    }
    red[tid] = lsum;
    __syncthreads();
    for (int s = 128; s > 0; s >>= 1) {
        if (tid < s) red[tid] += red[tid + s];
        __syncthreads();
    }
    float inv = 1.f / red[0];
#pragma unroll
    for (int i = 0; i < 16; i++) {
        int q = tid + i * 256;
        float pv = fmaxf(v[i] * inv * g_mm[q] * map, 1e-8f);
        prow[q] = __float2half_rn(pv);
    }
}

// ------------------------------------------------------------------
// rawT[m][q] -> fp16 (k=4, s=2, pad=1), m = o*16+ky*4+kx
// ------------------------------------------------------------------
__global__ void fill_raw_kernel(const float* __restrict__ x1) {
    int q = blockIdx.x * blockDim.x + threadIdx.x;
    int m = blockIdx.y;
    int o = m >> 4, kk = m & 15;
    int ky = kk >> 2, kx = kk & 3;
    int qi = q >> 6, qj = q & 63;
    int yy = 2 * qi - 1 + ky, xx = 2 * qj - 1 + kx;
    float v = 0.f;
    if (yy >= 0 && yy < H1N && xx >= 0 && xx < W1N)
        v = x1[(o * H1N + yy) * W1N + xx];
    g_rawh[(size_t)m * LP + q] = __float2half_rn(v);
}

// ------------------------------------------------------------------
// col2im gather: y[o,Y,X] = 0.25 * sum over <=4 entries of g_cols
// ------------------------------------------------------------------
__global__ void col2im_kernel(int b) {
    int idx = blockIdx.x * blockDim.x + threadIdx.x;
    int X = idx & 127;
    int Y = (idx >> 7) & 127;
    int o = idx >> 14;
    float acc = 0.f;
    int ky0 = (Y & 1) ? 0 : 1;
    int kx0 = (X & 1) ? 0 : 1;
#pragma unroll
    for (int t = 0; t < 2; t++) {
        int ky = ky0 + 2 * t;
        int i = (Y + 1 - ky) >> 1;
        if (i < 0 || i >= 64) continue;
#pragma unroll
        for (int u = 0; u < 2; u++) {
            int kx = kx0 + 2 * u;
            int j = (X + 1 - kx) >> 1;
            if (j < 0 || j >= 64) continue;
            acc += g_cols[(size_t)(o * 16 + ky * 4 + kx) * LP + i * 64 + j];
        }
    }
    g_y[(size_t)b * C1N * H1N * W1N + idx] = acc * 0.25f;
}

// ------------------------------------------------------------------
// final: 4 grouped dilated 3x3 convs (rates 1,2,4,8) + bias + relu
// ------------------------------------------------------------------
__global__ void __launch_bounds__(256) final_conv_kernel(
    const float* __restrict__ w, const float* __restrict__ bias, float* __restrict__ out)
{
    int tile = blockIdx.x;
    int g = blockIdx.y;
    int b = blockIdx.z;
    int r = 1 << g;  // rates 1,2,4,8
    int ty0 = (tile >> 3) * 16, tx0 = (tile & 7) * 16;
    int HW = 16 + 2 * r;
    __shared__ float yt[32 * 32];
    __shared__ float ws[144];
    int tid = threadIdx.x;
    int py = tid >> 4, px = tid & 15;

    float acc[16];
#pragma unroll
    for (int i = 0; i < 16; i++) acc[i] = 0.f;

    const float* yb = g_y + (size_t)b * C1N * H1N * W1N;
    for (int c = 0; c < C1N; c++) {
        for (int idx = tid; idx < HW * HW; idx += 256) {
            int iy = idx / HW, ix = idx % HW;
            int gy = ty0 - r + iy, gx = tx0 - r + ix;
            float v = 0.f;
            if (gy >= 0 && gy < H1N && gx >= 0 && gx < W1N)
                v = yb[(c * H1N + gy) * W1N + gx];
            yt[idx] = v;
        }
        if (tid < 144)
            ws[tid] = w[((g * 16 + tid / 9) * C1N + c) * 9 + tid % 9];
        __syncthreads();
#pragma unroll
        for (int ky = 0; ky < 3; ky++)
#pragma unroll
            for (int kx = 0; kx < 3; kx++) {
                float v = yt[(py + ky * r) * HW + px + kx * r];
#pragma unroll
                for (int oc = 0; oc < 16; oc++)
                    acc[oc] += v * ws[oc * 9 + ky * 3 + kx];
            }
        __syncthreads();
    }
    int Y = ty0 + py, X = tx0 + px;
#pragma unroll
    for (int oc = 0; oc < 16; oc++) {
        float o = acc[oc] + bias[g * 16 + oc];
        out[((size_t)(b * 64 + g * 16 + oc) * H1N + Y) * W1N + X] = fmaxf(o, 0.f);
    }
}

// ------------------------------------------------------------------
extern "C" void kernel_launch(void* const* d_in, const int* in_sizes, int n_in,
                              void* d_out, int out_size) {
    const float* x1       = (const float*)d_in[0];  // [4,128,128,128]
    const float* x2       = (const float*)d_in[1];  // [4,64,64,64]
    const float* mask     = (const float*)d_in[2];  // [4,1,128,128]
    const float* mask_all = (const float*)d_in[3];  // [4,1,64,64]
    const float* conv_w   = (const float*)d_in[4];  // [4,16,128,3,3]
    const float* conv_b   = (const float*)d_in[5];  // [4,16]
    float* out = (float*)d_out;

    for (int b = 0; b < BATCH; b++) {
        im2col_norm_kernel<<<LP, 256>>>(x2 + (size_t)b * C2N * H2N * W2N);
        mask_patch_kernel<<<LP / 256, 256>>>(mask + (size_t)b * H1N * W1N);
        gemm1_mma<<<dim3(32, 32), 256>>>();
        softmax_kernel<<<LP, 256>>>(mask_all + (size_t)b * LP);
        fill_raw_kernel<<<dim3(LP / 256, MRAW), 256>>>(x1 + (size_t)b * C1N * H1N * W1N);
        gemm2_mma<<<dim3(32, 16), 256>>>();
        col2im_kernel<<<(C1N * H1N * W1N) / 256, 256>>>(b);
    }
    final_conv_kernel<<<dim3(64, 4, 4), 256>>>(conv_w, conv_b, out);
}

// round 9
// speedup vs baseline: 3.9922x; 1.2767x over previous
#include <cuda_runtime.h>
#include <cuda_fp16.h>
#include <math.h>
#include <stdint.h>

#define BATCH 4
#define C1N 128
#define H1N 128
#define W1N 128
#define C2N 64
#define H2N 64
#define W2N 64
#define LP 4096          // H2*W2 positions / patches
#define KPATCH 576       // C2 * 3 * 3
#define MRAW 2048        // C1 * 4 * 4
#define SCALE_F 10.0f

// ---- scratch (device globals: allocation-free) ----
__device__ __half g_Ah[LP * KPATCH];        // im2col(x2) hi  [p][k]
__device__ __half g_Al[LP * KPATCH];        // im2col(x2) lo
__device__ float  g_invn[LP];
__device__ float  g_mm[LP];
__device__ float  g_S[(size_t)LP * LP];     // fp32 scores  [p][q]
__device__ __half g_P[(size_t)LP * LP];     // softmax out (fp16)  [p][q]
__device__ __half g_rawh[(size_t)MRAW * LP]; // rawT fp16 [m][q]
__device__ float  g_cols[(size_t)MRAW * LP]; // GEMM2 out [m][pos]
__device__ float  g_y[(size_t)BATCH * C1N * H1N * W1N];

// ==================================================================
// mma.sync fp16 + ldmatrix (base PTX, compiles at compute_103)
// ==================================================================
__device__ __forceinline__ void mma_f16(float d[4], const uint32_t a[4], const uint32_t b[2]) {
    asm volatile(
        "mma.sync.aligned.m16n8k16.row.col.f32.f16.f16.f32 "
        "{%0,%1,%2,%3},{%4,%5,%6,%7},{%8,%9},{%0,%1,%2,%3};"
        : "+f"(d[0]), "+f"(d[1]), "+f"(d[2]), "+f"(d[3])
        : "r"(a[0]), "r"(a[1]), "r"(a[2]), "r"(a[3]), "r"(b[0]), "r"(b[1]));
}
#define LDSM_X4(R, addr) \
    asm volatile("ldmatrix.sync.aligned.m8n8.x4.shared.b16 {%0,%1,%2,%3}, [%4];" \
        : "=r"((R)[0]), "=r"((R)[1]), "=r"((R)[2]), "=r"((R)[3]) : "r"(addr))

__device__ __forceinline__ uint32_t smem_u32(const void* p) {
    uint32_t a;
    asm("{ .reg .u64 t; cvta.to.shared.u64 t, %1; cvt.u32.u64 %0, t; }" : "=r"(a) : "l"(p));
    return a;
}

#define SSTR 20    // gemm1 smem row stride in u32 words (16 data + 4 pad)
#define SSTR2 36   // gemm2 smem row stride in u32 words (32 data + 4 pad)

// ==================================================================
// GEMM1 (symmetric): S[p][q] = <A_p, A_q> * invn[q].
// Only lower-triangle blocks (by <= bx); each writes its tile AND the
// transposed tile (scaled by invn[row]). fp16 2-term split, 3 MMA terms.
// M=N=4096, K=576, BK=32, 8 warps, 128x128 tile. 528 blocks.
// ==================================================================
__global__ void __launch_bounds__(256) gemm1_mma() {
    __shared__ uint32_t sAh[128 * SSTR], sAl[128 * SSTR];
    __shared__ uint32_t sBh[128 * SSTR], sBl[128 * SSTR];
    const int K = KPATCH;
    int t = threadIdx.x;

    // triangular block decode: bx >= by
    int L = blockIdx.x;
    int bx = (int)((sqrtf(8.f * (float)L + 1.f) - 1.f) * 0.5f);
    while ((bx + 1) * (bx + 2) / 2 <= L) bx++;
    while (bx * (bx + 1) / 2 > L) bx--;
    int by = L - bx * (bx + 1) / 2;

    int m0 = by * 128, n0 = bx * 128;
    int wid = t >> 5, lane = t & 31;
    int wm = (wid >> 1) * 32, wn = (wid & 1) * 64;
    int g = lane >> 2, tig = lane & 3;

    float acc[2][8][4] = {};

    int lm = t >> 1;              // row 0..127
    int lw = (t & 1) * 8;         // u32-word offset within 16-word row
    int sbase = lm * SSTR + lw;
    const __half* pAh = g_Ah + (size_t)(m0 + lm) * K + lw * 2;
    const __half* pAl = g_Al + (size_t)(m0 + lm) * K + lw * 2;
    const __half* pBh = g_Ah + (size_t)(n0 + lm) * K + lw * 2;
    const __half* pBl = g_Al + (size_t)(n0 + lm) * K + lw * 2;

    // ldmatrix per-lane source rows/column-halves
    int rowA = lane & 15;
    int koffA = ((lane >> 4) & 1) * 4;
    int rowB = (lane & 7) + ((lane & 16) >> 1);
    int koffB = ((lane & 8) >> 1);
    uint32_t aWh = smem_u32(sAh) + 4 * ((wm + rowA) * SSTR + koffA);
    uint32_t aWl = smem_u32(sAl) + 4 * ((wm + rowA) * SSTR + koffA);
    uint32_t bWh = smem_u32(sBh) + 4 * ((wn + rowB) * SSTR + koffB);
    uint32_t bWl = smem_u32(sBl) + 4 * ((wn + rowB) * SSTR + koffB);

    const int NC = K / 32;
    uint4 vah = *(const uint4*)pAh;
    uint4 vah2 = *(const uint4*)(pAh + 8);
    uint4 val_ = *(const uint4*)pAl;
    uint4 val2 = *(const uint4*)(pAl + 8);
    uint4 vbh = *(const uint4*)pBh;
    uint4 vbh2 = *(const uint4*)(pBh + 8);
    uint4 vbl = *(const uint4*)pBl;
    uint4 vbl2 = *(const uint4*)(pBl + 8);

    for (int ci = 0; ci < NC; ci++) {
        if (ci > 0) __syncthreads();
        *(uint4*)&sAh[sbase] = vah;  *(uint4*)&sAh[sbase + 4] = vah2;
        *(uint4*)&sAl[sbase] = val_; *(uint4*)&sAl[sbase + 4] = val2;
        *(uint4*)&sBh[sbase] = vbh;  *(uint4*)&sBh[sbase + 4] = vbh2;
        *(uint4*)&sBl[sbase] = vbl;  *(uint4*)&sBl[sbase + 4] = vbl2;
        __syncthreads();
        if (ci + 1 < NC) {
            int k0 = (ci + 1) * 32;
            vah = *(const uint4*)(pAh + k0);
            vah2 = *(const uint4*)(pAh + k0 + 8);
            val_ = *(const uint4*)(pAl + k0);
            val2 = *(const uint4*)(pAl + k0 + 8);
            vbh = *(const uint4*)(pBh + k0);
            vbh2 = *(const uint4*)(pBh + k0 + 8);
            vbl = *(const uint4*)(pBl + k0);
            vbl2 = *(const uint4*)(pBl + k0 + 8);
        }
#pragma unroll
        for (int s = 0; s < 2; s++) {
            uint32_t ah[2][4], al[2][4], bh[8][2], bl[8][2];
#pragma unroll
            for (int mt = 0; mt < 2; mt++) {
                uint32_t off = (uint32_t)(mt * 16 * SSTR + s * 8) * 4;
                LDSM_X4(ah[mt], aWh + off);
                LDSM_X4(al[mt], aWl + off);
            }
#pragma unroll
            for (int ntp = 0; ntp < 4; ntp++) {
                uint32_t off = (uint32_t)(ntp * 16 * SSTR + s * 8) * 4;
                LDSM_X4(&bh[2 * ntp][0], bWh + off);
                LDSM_X4(&bl[2 * ntp][0], bWl + off);
            }
#pragma unroll
            for (int mt = 0; mt < 2; mt++)
#pragma unroll
                for (int nt = 0; nt < 8; nt++) {
                    mma_f16(acc[mt][nt], ah[mt], bh[nt]);
                    mma_f16(acc[mt][nt], ah[mt], bl[nt]);
                    mma_f16(acc[mt][nt], al[mt], bh[nt]);
                }
        }
    }
    // epilogue: write tile (scale invn[col]) and transpose (scale invn[row])
#pragma unroll
    for (int mt = 0; mt < 2; mt++) {
        int row = m0 + wm + mt * 16 + g;
        float sr0 = __ldg(&g_invn[row]);
        float sr8 = __ldg(&g_invn[row + 8]);
#pragma unroll
        for (int nt = 0; nt < 8; nt++) {
            int col = n0 + wn + nt * 8 + 2 * tig;
            float s0 = __ldg(&g_invn[col]);
            float s1 = __ldg(&g_invn[col + 1]);
            *(float2*)(g_S + (size_t)row * LP + col) =
                make_float2(acc[mt][nt][0] * s0, acc[mt][nt][1] * s1);
            *(float2*)(g_S + (size_t)(row + 8) * LP + col) =
                make_float2(acc[mt][nt][2] * s0, acc[mt][nt][3] * s1);
            // transpose tile
            g_S[(size_t)col * LP + row]           = acc[mt][nt][0] * sr0;
            g_S[(size_t)(col + 1) * LP + row]     = acc[mt][nt][1] * sr0;
            g_S[(size_t)col * LP + row + 8]       = acc[mt][nt][2] * sr8;
            g_S[(size_t)(col + 1) * LP + row + 8] = acc[mt][nt][3] * sr8;
        }
    }
}

// ==================================================================
// GEMM2: cols[m][p] = sum_q raw[m][q] * P[p][q]
// A = raw single fp16, B = P single fp16 (1 MMA term).
// M=2048, N=4096, K=4096, BK=64, 8 warps, 128x128 tile.
// ==================================================================
__global__ void __launch_bounds__(256) gemm2_mma() {
    __shared__ uint32_t sA[128 * SSTR2];
    __shared__ uint32_t sB[128 * SSTR2];
    int t = threadIdx.x;
    int m0 = blockIdx.y * 128, n0 = blockIdx.x * 128;
    int wid = t >> 5, lane = t & 31;
    int wm = (wid >> 1) * 32, wn = (wid & 1) * 64;
    int g = lane >> 2, tig = lane & 3;

    float acc[2][8][4] = {};

    int lm = t >> 1;
    int lw = (t & 1) * 16;        // u32-word offset (half of 32-word row)
    int sbase = lm * SSTR2 + lw;
    const __half* pA = g_rawh + (size_t)(m0 + lm) * LP + lw * 2;
    const __half* pB = g_P    + (size_t)(n0 + lm) * LP + lw * 2;

    int rowA = lane & 15;
    int koffA = ((lane >> 4) & 1) * 4;
    int rowB = (lane & 7) + ((lane & 16) >> 1);
    int koffB = ((lane & 8) >> 1);
    uint32_t aW = smem_u32(sA) + 4 * ((wm + rowA) * SSTR2 + koffA);
    uint32_t bW = smem_u32(sB) + 4 * ((wn + rowB) * SSTR2 + koffB);

    const int NC = LP / 64;
    uint4 va[4], vb[4];
#pragma unroll
    for (int j = 0; j < 4; j++) {
        va[j] = *(const uint4*)(pA + j * 8);
        vb[j] = *(const uint4*)(pB + j * 8);
    }

    for (int ci = 0; ci < NC; ci++) {
        if (ci > 0) __syncthreads();
#pragma unroll
        for (int j = 0; j < 4; j++) {
            *(uint4*)&sA[sbase + j * 4] = va[j];
            *(uint4*)&sB[sbase + j * 4] = vb[j];
        }
        __syncthreads();
        if (ci + 1 < NC) {
            int k0 = (ci + 1) * 64;
#pragma unroll
            for (int j = 0; j < 4; j++) {
                va[j] = *(const uint4*)(pA + k0 + j * 8);
                vb[j] = *(const uint4*)(pB + k0 + j * 8);
            }
        }
#pragma unroll
        for (int s = 0; s < 4; s++) {
            uint32_t a[2][4], b[8][2];
#pragma unroll
            for (int mt = 0; mt < 2; mt++) {
                uint32_t off = (uint32_t)(mt * 16 * SSTR2 + s * 8) * 4;
                LDSM_X4(a[mt], aW + off);
            }
#pragma unroll
            for (int ntp = 0; ntp < 4; ntp++) {
                uint32_t off = (uint32_t)(ntp * 16 * SSTR2 + s * 8) * 4;
                LDSM_X4(&b[2 * ntp][0], bW + off);
            }
#pragma unroll
            for (int mt = 0; mt < 2; mt++)
#pragma unroll
                for (int nt = 0; nt < 8; nt++)
                    mma_f16(acc[mt][nt], a[mt], b[nt]);
        }
    }
#pragma unroll
    for (int mt = 0; mt < 2; mt++) {
        int row = m0 + wm + mt * 16 + g;
#pragma unroll
        for (int nt = 0; nt < 8; nt++) {
            int col = n0 + wn + nt * 8 + 2 * tig;
            *(float2*)(g_cols + (size_t)row * LP + col) =
                make_float2(acc[mt][nt][0], acc[mt][nt][1]);
            *(float2*)(g_cols + (size_t)(row + 8) * LP + col) =
                make_float2(acc[mt][nt][2], acc[mt][nt][3]);
        }
    }
}

// ------------------------------------------------------------------
// im2col of x2 (k=3,s=1,pad=1) -> fp16 hi/lo split + inverse norms
// ------------------------------------------------------------------
__global__ void im2col_norm_kernel(const float* __restrict__ x2) {
    int p = blockIdx.x;
    int pi = p >> 6, pj = p & 63;
    int tid = threadIdx.x;
    float ss = 0.f;
    for (int k = tid; k < KPATCH; k += 256) {
        int c = k / 9, ki = k % 9;
        int ky = ki / 3, kx = ki % 3;
        int yy = pi - 1 + ky, xx = pj - 1 + kx;
        float v = 0.f;
        if (yy >= 0 && yy < H2N && xx >= 0 && xx < W2N)
            v = x2[(c * H2N + yy) * W2N + xx];
        __half h = __float2half_rn(v);
        g_Ah[p * KPATCH + k] = h;
        g_Al[p * KPATCH + k] = __float2half_rn(v - __half2float(h));
        ss += v * v;
    }
    __shared__ float red[256];
    red[tid] = ss;
    __syncthreads();
    for (int s = 128; s > 0; s >>= 1) {
        if (tid < s) red[tid] += red[tid + s];
        __syncthreads();
    }
    if (tid == 0) {
        float n = sqrtf(red[0]);
        g_invn[p] = 1.f / fmaxf(n, 1e-4f);
    }
}

// ------------------------------------------------------------------
// mask patches (k=4,s=2,pad=1): mm[q] = (sum == 0) ? 1 : 0
// ------------------------------------------------------------------
__global__ void mask_patch_kernel(const float* __restrict__ mask) {
    int q = blockIdx.x * blockDim.x + threadIdx.x;
    if (q >= LP) return;
    int qi = q >> 6, qj = q & 63;
    float s = 0.f;
    for (int ky = 0; ky < 4; ky++)
        for (int kx = 0; kx < 4; kx++) {
            int yy = 2 * qi - 1 + ky, xx = 2 * qj - 1 + kx;
            if (yy >= 0 && yy < H1N && xx >= 0 && xx < W1N)
                s += mask[yy * W1N + xx];
        }
    g_mm[q] = (s == 0.f) ? 1.f : 0.f;
}

// ------------------------------------------------------------------
// masked softmax over q for each row p; writes fp16 P
// ------------------------------------------------------------------
__global__ void __launch_bounds__(256) softmax_kernel(const float* __restrict__ mask_all) {
    int p = blockIdx.x;
    int tid = threadIdx.x;
    float map = mask_all[p];
    const float* row = g_S + (size_t)p * LP;
    __half* prow = g_P + (size_t)p * LP;

    float v[16];
    float lmax = -1e30f;
#pragma unroll
    for (int i = 0; i < 16; i++) {
        int q = tid + i * 256;
        float x = row[q] * g_mm[q] * map;
        v[i] = x;
        lmax = fmaxf(lmax, x);
    }
    __shared__ float red[256];
    red[tid] = lmax;
    __syncthreads();
    for (int s = 128; s > 0; s >>= 1) {
        if (tid < s) red[tid] = fmaxf(red[tid], red[tid + s]);
        __syncthreads();
    }
    float gmax = red[0];
    __syncthreads();

    float lsum = 0.f;
#pragma unroll
    for (int i = 0; i < 16; i++) {
        float e = expf(SCALE_F * (v[i] - gmax));
        v[i] = e;
        lsum += e;
    }
    red[tid] = lsum;
    __syncthreads();
    for (int s = 128; s > 0; s >>= 1) {
        if (tid < s) red[tid] += red[tid + s];
        __syncthreads();
    }
    float inv = 1.f / red[0];
#pragma unroll
    for (int i = 0; i < 16; i++) {
        int q = tid + i * 256;
        float pv = fmaxf(v[i] * inv * g_mm[q] * map, 1e-8f);
        prow[q] = __float2half_rn(pv);
    }
}

// ------------------------------------------------------------------
// rawT[m][q] -> fp16 (k=4, s=2, pad=1), m = o*16+ky*4+kx
// ------------------------------------------------------------------
__global__ void fill_raw_kernel(const float* __restrict__ x1) {
    int q = blockIdx.x * blockDim.x + threadIdx.x;
    int m = blockIdx.y;
    int o = m >> 4, kk = m & 15;
    int ky = kk >> 2, kx = kk & 3;
    int qi = q >> 6, qj = q & 63;
    int yy = 2 * qi - 1 + ky, xx = 2 * qj - 1 + kx;
    float v = 0.f;
    if (yy >= 0 && yy < H1N && xx >= 0 && xx < W1N)
        v = x1[(o * H1N + yy) * W1N + xx];
    g_rawh[(size_t)m * LP + q] = __float2half_rn(v);
}

// ------------------------------------------------------------------
// col2im gather: y[o,Y,X] = 0.25 * sum over <=4 entries of g_cols
// ------------------------------------------------------------------
__global__ void col2im_kernel(int b) {
    int idx = blockIdx.x * blockDim.x + threadIdx.x;
    int X = idx & 127;
    int Y = (idx >> 7) & 127;
    int o = idx >> 14;
    float acc = 0.f;
    int ky0 = (Y & 1) ? 0 : 1;
    int kx0 = (X & 1) ? 0 : 1;
#pragma unroll
    for (int t = 0; t < 2; t++) {
        int ky = ky0 + 2 * t;
        int i = (Y + 1 - ky) >> 1;
        if (i < 0 || i >= 64) continue;
#pragma unroll
        for (int u = 0; u < 2; u++) {
            int kx = kx0 + 2 * u;
            int j = (X + 1 - kx) >> 1;
            if (j < 0 || j >= 64) continue;
            acc += g_cols[(size_t)(o * 16 + ky * 4 + kx) * LP + i * 64 + j];
        }
    }
    g_y[(size_t)b * C1N * H1N * W1N + idx] = acc * 0.25f;
}

// ------------------------------------------------------------------
// final: 4 grouped dilated 3x3 convs (rates 1,2,4,8) + bias + relu
// ------------------------------------------------------------------
__global__ void __launch_bounds__(256) final_conv_kernel(
    const float* __restrict__ w, const float* __restrict__ bias, float* __restrict__ out)
{
    int tile = blockIdx.x;
    int g = blockIdx.y;
    int b = blockIdx.z;
    int r = 1 << g;  // rates 1,2,4,8
    int ty0 = (tile >> 3) * 16, tx0 = (tile & 7) * 16;
    int HW = 16 + 2 * r;
    __shared__ float yt[32 * 32];
    __shared__ float ws[144];
    int tid = threadIdx.x;
    int py = tid >> 4, px = tid & 15;

    float acc[16];
#pragma unroll
    for (int i = 0; i < 16; i++) acc[i] = 0.f;

    const float* yb = g_y + (size_t)b * C1N * H1N * W1N;
    for (int c = 0; c < C1N; c++) {
        for (int idx = tid; idx < HW * HW; idx += 256) {
            int iy = idx / HW, ix = idx % HW;
            int gy = ty0 - r + iy, gx = tx0 - r + ix;
            float v = 0.f;
            if (gy >= 0 && gy < H1N && gx >= 0 && gx < W1N)
                v = yb[(c * H1N + gy) * W1N + gx];
            yt[idx] = v;
        }
        if (tid < 144)
            ws[tid] = w[((g * 16 + tid / 9) * C1N + c) * 9 + tid % 9];
        __syncthreads();
#pragma unroll
        for (int ky = 0; ky < 3; ky++)
#pragma unroll
            for (int kx = 0; kx < 3; kx++) {
                float v = yt[(py + ky * r) * HW + px + kx * r];
#pragma unroll
                for (int oc = 0; oc < 16; oc++)
                    acc[oc] += v * ws[oc * 9 + ky * 3 + kx];
            }
        __syncthreads();
    }
    int Y = ty0 + py, X = tx0 + px;
#pragma unroll
    for (int oc = 0; oc < 16; oc++) {
        float o = acc[oc] + bias[g * 16 + oc];
        out[((size_t)(b * 64 + g * 16 + oc) * H1N + Y) * W1N + X] = fmaxf(o, 0.f);
    }
}

// ------------------------------------------------------------------
extern "C" void kernel_launch(void* const* d_in, const int* in_sizes, int n_in,
                              void* d_out, int out_size) {
    const float* x1       = (const float*)d_in[0];  // [4,128,128,128]
    const float* x2       = (const float*)d_in[1];  // [4,64,64,64]
    const float* mask     = (const float*)d_in[2];  // [4,1,128,128]
    const float* mask_all = (const float*)d_in[3];  // [4,1,64,64]
    const float* conv_w   = (const float*)d_in[4];  // [4,16,128,3,3]
    const float* conv_b   = (const float*)d_in[5];  // [4,16]
    float* out = (float*)d_out;

    for (int b = 0; b < BATCH; b++) {
        im2col_norm_kernel<<<LP, 256>>>(x2 + (size_t)b * C2N * H2N * W2N);
        mask_patch_kernel<<<LP / 256, 256>>>(mask + (size_t)b * H1N * W1N);
        gemm1_mma<<<528, 256>>>();
        softmax_kernel<<<LP, 256>>>(mask_all + (size_t)b * LP);
        fill_raw_kernel<<<dim3(LP / 256, MRAW), 256>>>(x1 + (size_t)b * C1N * H1N * W1N);
        gemm2_mma<<<dim3(32, 16), 256>>>();
        col2im_kernel<<<(C1N * H1N * W1N) / 256, 256>>>(b);
    }
    final_conv_kernel<<<dim3(64, 4, 4), 256>>>(conv_w, conv_b, out);
}